// round 14
// baseline (speedup 1.0000x reference)
#include <cuda_runtime.h>
#include <cuda_bf16.h>
#include <math.h>
#include <stdint.h>

// ---------------- problem constants ----------------
#define NND 32768
#define NE  262144
#define NS  128
#define D_0 190
#define D_X 380
#define D_GIN 256
#define D_GH 512

// ---------------- device scratch (static, no allocation) ----------------
__device__ __align__(128) float g_x1[(size_t)NND * D_X];
__device__ __align__(128) __nv_bfloat16 g_ahi[(size_t)NND * 1024];
__device__ __align__(128) __nv_bfloat16 g_alo[(size_t)NND * 1024];
__device__ __align__(128) __nv_bfloat16 g_rhi[(size_t)NND * D_GH];
__device__ __align__(128) __nv_bfloat16 g_rlo[(size_t)NND * D_GH];
__device__ __align__(128) __nv_bfloat16 g_whi[512 * 1024];
__device__ __align__(128) __nv_bfloat16 g_wlo[512 * 1024];
__device__ float g_invdeg[NND];
__device__ int   g_segid[NND];
__device__ int   g_deg[NND];
__device__ int   g_rowstart[NND + 1];
__device__ int   g_cursor[NND];
__device__ int   g_csrsrc[NE];
__device__ float g_glnstat[NS * 2];
__device__ float g_glnsum[NS];
__device__ float g_glnss[NS];
__device__ float g_colsum[D_GH];
__device__ float g_pnmean[D_GH];
__device__ float g_scalar[2];
__device__ float g_segout[NS];

// ---------------- PTX helpers (compute_103-safe) ----------------
__device__ __forceinline__ uint32_t smem_u32(const void* p) {
    uint32_t a;
    asm("{ .reg .u64 t; cvta.to.shared.u64 t, %1; cvt.u32.u64 %0, t; }" : "=r"(a) : "l"(p));
    return a;
}
__device__ __forceinline__ void cpasync16(uint32_t dst, const void* src) {
    asm volatile("cp.async.cg.shared.global [%0], [%1], 16;" :: "r"(dst), "l"(src) : "memory");
}
__device__ __forceinline__ void ldm_x4(uint32_t* r, uint32_t addr) {
    asm volatile("ldmatrix.sync.aligned.m8n8.x4.shared.b16 {%0,%1,%2,%3},[%4];"
                 : "=r"(r[0]), "=r"(r[1]), "=r"(r[2]), "=r"(r[3]) : "r"(addr));
}
__device__ __forceinline__ void ldm_x2(uint32_t* r, uint32_t addr) {
    asm volatile("ldmatrix.sync.aligned.m8n8.x2.shared.b16 {%0,%1},[%2];"
                 : "=r"(r[0]), "=r"(r[1]) : "r"(addr));
}
__device__ __forceinline__ void mma_bf16(float* d, const uint32_t* a, const uint32_t* b) {
    asm volatile(
        "mma.sync.aligned.m16n8k16.row.col.f32.bf16.bf16.f32 "
        "{%0,%1,%2,%3}, {%4,%5,%6,%7}, {%8,%9}, {%0,%1,%2,%3};"
        : "+f"(d[0]), "+f"(d[1]), "+f"(d[2]), "+f"(d[3])
        : "r"(a[0]), "r"(a[1]), "r"(a[2]), "r"(a[3]), "r"(b[0]), "r"(b[1]));
}
__device__ __forceinline__ void split_bf16(float v, __nv_bfloat16& h, __nv_bfloat16& l) {
    h = __float2bfloat16(v);
    l = __float2bfloat16(v - __bfloat162float(h));
}

// ---------------- small utility kernels ----------------
__global__ void k_segid(const int* __restrict__ sep) {
    int i = blockIdx.x * blockDim.x + threadIdx.x;
    if (i >= NND) return;
    int lo = 0, hi = NS;
    while (lo < hi) { int mid = (lo + hi) >> 1; if (sep[mid] <= i) lo = mid + 1; else hi = mid; }
    g_segid[i] = lo;
    g_deg[i] = 0;
}
__global__ void k_hist(const int* __restrict__ dst) {
    int e = blockIdx.x * blockDim.x + threadIdx.x;
    if (e < NE) atomicAdd(&g_deg[dst[e]], 1);
}
// one-block scan over degrees; also zeroes all stat accumulators
__global__ void __launch_bounds__(1024) k_scan() {
    __shared__ int sh[1024];
    int t = threadIdx.x;
    if (t < D_GH) g_colsum[t] = 0.f;
    if (t < 2) g_scalar[t] = 0.f;
    if (t < NS) { g_segout[t] = 0.f; g_glnsum[t] = 0.f; g_glnss[t] = 0.f; }
    int base = t * 32;
    int loc[32];
    int s = 0;
#pragma unroll
    for (int i = 0; i < 32; i++) { loc[i] = s; s += g_deg[base + i]; }
    sh[t] = s;
    __syncthreads();
    for (int o = 1; o < 1024; o <<= 1) {
        int v = (t >= o) ? sh[t - o] : 0;
        __syncthreads();
        sh[t] += v;
        __syncthreads();
    }
    int start = (t == 0) ? 0 : sh[t - 1];
#pragma unroll
    for (int i = 0; i < 32; i++) {
        int n = base + i;
        int st = start + loc[i];
        g_rowstart[n] = st;
        g_cursor[n] = st;
        int d = g_deg[n];
        g_invdeg[n] = 1.f / (float)((d > 1) ? d : 1);
    }
    if (t == 1023) g_rowstart[NND] = sh[1023];
}
__global__ void k_fillcsr(const int* __restrict__ src, const int* __restrict__ dst) {
    int e = blockIdx.x * blockDim.x + threadIdx.x;
    if (e >= NE) return;
    int d = dst[e];
    int pos = atomicAdd(&g_cursor[d], 1);
    g_csrsrc[pos] = src[e];
}
__global__ void k_concat_cvt(const float* __restrict__ nf, const float* __restrict__ ncf,
                             const float* __restrict__ emb, const int* __restrict__ ops,
                             __nv_bfloat16* __restrict__ hi, __nv_bfloat16* __restrict__ lo) {
    size_t i = (size_t)blockIdx.x * blockDim.x + threadIdx.x;
    if (i >= (size_t)NND * 192) return;
    int r = (int)(i / 192);
    int c = (int)(i - (size_t)r * 192);
    float v = 0.f;
    if (c < 90)       v = nf[(size_t)r * 90 + c];
    else if (c < 126) v = ncf[(size_t)r * 36 + (c - 90)];
    else if (c < 190) v = emb[(size_t)ops[r] * 64 + (c - 126)];
    __nv_bfloat16 h, l;
    split_bf16(v, h, l);
    hi[i] = h; lo[i] = l;
}
__global__ void k_cvtW(const float* __restrict__ W, __nv_bfloat16* __restrict__ hi,
                       __nv_bfloat16* __restrict__ lo, int Nd, int K, int Ndp, int Kp) {
    int idx = blockIdx.x * blockDim.x + threadIdx.x;
    if (idx >= Ndp * Kp) return;
    int n = idx / Kp, k = idx - n * Kp;
    float v = (n < Nd && k < K) ? W[(size_t)n * K + k] : 0.f;
    __nv_bfloat16 h, l;
    split_bf16(v, h, l);
    hi[idx] = h; lo[idx] = l;
}
__global__ void k_cvtWpair(const float* __restrict__ wl, const float* __restrict__ wr,
                           __nv_bfloat16* __restrict__ hi, __nv_bfloat16* __restrict__ lo, int K1) {
    int Kt = 2 * K1;
    int idx = blockIdx.x * blockDim.x + threadIdx.x;
    if (idx >= 512 * Kt) return;
    int n = idx / Kt, k = idx - n * Kt;
    float v = (k < K1) ? wl[(size_t)n * K1 + k] : wr[(size_t)n * K1 + (k - K1)];
    __nv_bfloat16 h, l;
    split_bf16(v, h, l);
    hi[idx] = h; lo[idx] = l;
}

// ---------------- CSR gather with fused graph-LN (D=256) ----------------
// Input: raw MLP2 output bf16 hi/lo in rhi/rlo (stride 256).
// Applies (v - mean[seg(src)]) * invstd[seg(src)] * gamma[f] + beta[f] inline.
// Output A-buffer (stride 512): agg of normalized neighbors -> cols [0,256);
//                               normalized self            -> cols [256,512).
__global__ void __launch_bounds__(256)
k_gather_gln(const __nv_bfloat16* __restrict__ rhi, const __nv_bfloat16* __restrict__ rlo,
             const float* __restrict__ gamma, const float* __restrict__ beta,
             __nv_bfloat16* __restrict__ hi, __nv_bfloat16* __restrict__ lo) {
    const int warp = (blockIdx.x * blockDim.x + threadIdx.x) >> 5;
    if (warp >= NND) return;
    const int lane = threadIdx.x & 31;
    float gm[8], bt[8];
#pragma unroll
    for (int q = 0; q < 8; q++) {
        gm[q] = gamma[lane * 8 + q];
        bt[q] = beta[lane * 8 + q];
    }
    // self
    {
        int seg = g_segid[warp];
        float m = g_glnstat[2 * seg], is = g_glnstat[2 * seg + 1];
        size_t sb = (size_t)warp * 256 + (size_t)lane * 8;
        uint4 h4 = *(const uint4*)(rhi + sb);
        uint4 l4 = *(const uint4*)(rlo + sb);
        const __nv_bfloat162* hp = (const __nv_bfloat162*)&h4;
        const __nv_bfloat162* lp = (const __nv_bfloat162*)&l4;
        __nv_bfloat162 hv[4], lv[4];
#pragma unroll
        for (int q = 0; q < 4; q++) {
            float2 hf = __bfloat1622float2(hp[q]);
            float2 lf = __bfloat1622float2(lp[q]);
            float v0 = (hf.x + lf.x - m) * is * gm[2 * q + 0] + bt[2 * q + 0];
            float v1 = (hf.y + lf.y - m) * is * gm[2 * q + 1] + bt[2 * q + 1];
            __nv_bfloat16 h0, l0, h1, l1;
            split_bf16(v0, h0, l0);
            split_bf16(v1, h1, l1);
            hv[q] = __nv_bfloat162{h0, h1};
            lv[q] = __nv_bfloat162{l0, l1};
        }
        size_t ob = (size_t)warp * 512 + 256 + (size_t)lane * 8;
        *(uint4*)(hi + ob) = *(const uint4*)hv;
        *(uint4*)(lo + ob) = *(const uint4*)lv;
    }
    // neighbors
    const int s0 = g_rowstart[warp];
    const int s1 = g_rowstart[warp + 1];
    float acc[8];
#pragma unroll
    for (int q = 0; q < 8; q++) acc[q] = 0.f;
    for (int e = s0; e < s1; e++) {
        int s = g_csrsrc[e];
        int seg = g_segid[s];
        float m = g_glnstat[2 * seg], is = g_glnstat[2 * seg + 1];
        size_t base = (size_t)s * 256 + (size_t)lane * 8;
        uint4 h4 = *(const uint4*)(rhi + base);
        uint4 l4 = *(const uint4*)(rlo + base);
        const __nv_bfloat162* hp = (const __nv_bfloat162*)&h4;
        const __nv_bfloat162* lp = (const __nv_bfloat162*)&l4;
#pragma unroll
        for (int q = 0; q < 4; q++) {
            float2 hf = __bfloat1622float2(hp[q]);
            float2 lf = __bfloat1622float2(lp[q]);
            acc[2 * q + 0] += (hf.x + lf.x - m) * is * gm[2 * q + 0] + bt[2 * q + 0];
            acc[2 * q + 1] += (hf.y + lf.y - m) * is * gm[2 * q + 1] + bt[2 * q + 1];
        }
    }
    const float inv = g_invdeg[warp];
    __nv_bfloat162 hv[4], lv[4];
#pragma unroll
    for (int q = 0; q < 4; q++) {
        __nv_bfloat16 h0, l0, h1, l1;
        split_bf16(acc[2 * q + 0] * inv, h0, l0);
        split_bf16(acc[2 * q + 1] * inv, h1, l1);
        hv[q] = __nv_bfloat162{h0, h1};
        lv[q] = __nv_bfloat162{l0, l1};
    }
    size_t ob = (size_t)warp * 512 + (size_t)lane * 8;
    *(uint4*)(hi + ob) = *(const uint4*)hv;
    *(uint4*)(lo + ob) = *(const uint4*)lv;
}

// ---------------- CSR gather with fused PairNorm+ReLU (D=512) ----------------
__global__ void __launch_bounds__(256)
k_gather_pn(const __nv_bfloat16* __restrict__ rhi, const __nv_bfloat16* __restrict__ rlo,
            __nv_bfloat16* __restrict__ hi, __nv_bfloat16* __restrict__ lo) {
    const int warp = (blockIdx.x * blockDim.x + threadIdx.x) >> 5;
    if (warp >= NND) return;
    const int lane = threadIdx.x & 31;
    const float sc = g_scalar[1];
    float mean[2][8];
#pragma unroll
    for (int w = 0; w < 2; w++)
#pragma unroll
        for (int q = 0; q < 8; q++) mean[w][q] = g_pnmean[w * 256 + lane * 8 + q];

    {
        size_t sb = (size_t)warp * 512 + (size_t)lane * 8;
        size_t ob = (size_t)warp * 1024 + 512 + (size_t)lane * 8;
#pragma unroll
        for (int w = 0; w < 2; w++) {
            uint4 h4 = *(const uint4*)(rhi + sb + w * 256);
            uint4 l4 = *(const uint4*)(rlo + sb + w * 256);
            const __nv_bfloat162* hp = (const __nv_bfloat162*)&h4;
            const __nv_bfloat162* lp = (const __nv_bfloat162*)&l4;
            __nv_bfloat162 hv[4], lv[4];
#pragma unroll
            for (int q = 0; q < 4; q++) {
                float2 hf = __bfloat1622float2(hp[q]);
                float2 lf = __bfloat1622float2(lp[q]);
                float v0 = fmaxf((hf.x + lf.x - mean[w][2 * q + 0]) * sc, 0.f);
                float v1 = fmaxf((hf.y + lf.y - mean[w][2 * q + 1]) * sc, 0.f);
                __nv_bfloat16 h0, l0, h1, l1;
                split_bf16(v0, h0, l0);
                split_bf16(v1, h1, l1);
                hv[q] = __nv_bfloat162{h0, h1};
                lv[q] = __nv_bfloat162{l0, l1};
            }
            *(uint4*)(hi + ob + w * 256) = *(const uint4*)hv;
            *(uint4*)(lo + ob + w * 256) = *(const uint4*)lv;
        }
    }

    const int s0 = g_rowstart[warp];
    const int s1 = g_rowstart[warp + 1];
    float acc[2][8];
#pragma unroll
    for (int w = 0; w < 2; w++)
#pragma unroll
        for (int q = 0; q < 8; q++) acc[w][q] = 0.f;
    for (int e = s0; e < s1; e++) {
        int s = g_csrsrc[e];
        size_t base = (size_t)s * 512 + (size_t)lane * 8;
#pragma unroll
        for (int w = 0; w < 2; w++) {
            uint4 h4 = *(const uint4*)(rhi + base + w * 256);
            uint4 l4 = *(const uint4*)(rlo + base + w * 256);
            const __nv_bfloat162* hp = (const __nv_bfloat162*)&h4;
            const __nv_bfloat162* lp = (const __nv_bfloat162*)&l4;
#pragma unroll
            for (int q = 0; q < 4; q++) {
                float2 hf = __bfloat1622float2(hp[q]);
                float2 lf = __bfloat1622float2(lp[q]);
                acc[w][2 * q + 0] += fmaxf((hf.x + lf.x - mean[w][2 * q + 0]) * sc, 0.f);
                acc[w][2 * q + 1] += fmaxf((hf.y + lf.y - mean[w][2 * q + 1]) * sc, 0.f);
            }
        }
    }
    const float inv = g_invdeg[warp];
    size_t ob = (size_t)warp * 1024 + (size_t)lane * 8;
#pragma unroll
    for (int w = 0; w < 2; w++) {
        __nv_bfloat162 hv[4], lv[4];
#pragma unroll
        for (int q = 0; q < 4; q++) {
            __nv_bfloat16 h0, l0, h1, l1;
            split_bf16(acc[w][2 * q + 0] * inv, h0, l0);
            split_bf16(acc[w][2 * q + 1] * inv, h1, l1);
            hv[q] = __nv_bfloat162{h0, h1};
            lv[q] = __nv_bfloat162{l0, l1};
        }
        *(uint4*)(hi + ob + w * 256) = *(const uint4*)hv;
        *(uint4*)(lo + ob + w * 256) = *(const uint4*)lv;
    }
}

// ---------------- mma.sync bf16x3 GEMM (BK=32, 2 CTAs/SM) ----------------
// flags: 2 = leaky-relu, 4 = fused segment-dot, 8 = raw-bf16 out + pairnorm stats,
//        16 = gln stats, 32 = raw-bf16 out (stride Nd). MLP2 uses 32|16; SAGE uses 8.
#define MAT_BYTES 10240
#define STG_BYTES 40960
#define GSMEM (2 * STG_BYTES)

__global__ void __launch_bounds__(256, 2)
k_mmagemm(const __nv_bfloat16* __restrict__ Ahi, const __nv_bfloat16* __restrict__ Alo,
          const __nv_bfloat16* __restrict__ Whi, const __nv_bfloat16* __restrict__ Wlo,
          const float* __restrict__ bias, float* __restrict__ C,
          __nv_bfloat16* __restrict__ Rhi, __nv_bfloat16* __restrict__ Rlo,
          const float* __restrict__ wc, int Kp, int Nd, int flags)
{
    extern __shared__ char smc[];
    const uint32_t sbase = smem_u32(smc);
    const int tid = threadIdx.x;
    const int lane = tid & 31;
    const int wid = tid >> 5;
    const int wm = wid & 1;
    const int wn = wid >> 1;
    const int bm = blockIdx.y * 128;
    const int bn = blockIdx.x * 128;

    const __nv_bfloat16* gsrc[4] = {Ahi, Alo, Whi, Wlo};
    const int rbase[4] = {bm, bm, bn, bn};
    const int nc = Kp >> 5;

    const uint32_t abyte = (uint32_t)((wm * 64 + (lane & 15)) * 80 + ((lane >> 4) & 1) * 16);
    const uint32_t bbyte = (uint32_t)((wn * 32 + (lane & 7)) * 80 + ((lane >> 3) & 1) * 16);

    float acc[4][4][4];
#pragma unroll
    for (int i = 0; i < 4; i++)
#pragma unroll
        for (int j = 0; j < 4; j++)
#pragma unroll
            for (int q = 0; q < 4; q++) acc[i][j][q] = 0.f;

    auto load_chunk = [&](int c) {
        const int k0 = c * 32;
        const uint32_t sdst0 = sbase + (uint32_t)(c & 1) * STG_BYTES;
#pragma unroll
        for (int t = 0; t < 8; t++) {
            int idx = tid + t * 256;
            int mat = idx >> 9;
            int u = idx & 511;
            int row = u >> 2, seg = u & 3;
            uint32_t dst = sdst0 + (uint32_t)mat * MAT_BYTES + (uint32_t)(row * 80 + seg * 16);
            const __nv_bfloat16* src = gsrc[mat] + (size_t)(rbase[mat] + row) * Kp + k0 + seg * 8;
            cpasync16(dst, src);
        }
        asm volatile("cp.async.commit_group;" ::: "memory");
    };

    load_chunk(0);

    for (int c = 0; c < nc; c++) {
        if (c + 1 < nc) {
            load_chunk(c + 1);
            asm volatile("cp.async.wait_group 1;" ::: "memory");
        } else {
            asm volatile("cp.async.wait_group 0;" ::: "memory");
        }
        __syncthreads();

        const uint32_t st = sbase + (uint32_t)(c & 1) * STG_BYTES;
        const uint32_t aHI = st + abyte;
        const uint32_t aLO = st + MAT_BYTES + abyte;
        const uint32_t wHI = st + 2 * MAT_BYTES + bbyte;
        const uint32_t wLO = st + 3 * MAT_BYTES + bbyte;

#pragma unroll
        for (int ks = 0; ks < 2; ks++) {
            uint32_t wh[4][2], wl[4][2];
#pragma unroll
            for (int j = 0; j < 4; j++) {
                ldm_x2(wh[j], wHI + (uint32_t)(j * 640 + ks * 32));
                ldm_x2(wl[j], wLO + (uint32_t)(j * 640 + ks * 32));
            }
#pragma unroll
            for (int i = 0; i < 4; i++) {
                uint32_t ah[4], al[4];
                ldm_x4(ah, aHI + (uint32_t)(i * 1280 + ks * 32));
                ldm_x4(al, aLO + (uint32_t)(i * 1280 + ks * 32));
#pragma unroll
                for (int j = 0; j < 4; j++) {
                    mma_bf16(acc[i][j], ah, wh[j]);
                    mma_bf16(acc[i][j], ah, wl[j]);
                    mma_bf16(acc[i][j], al, wh[j]);
                }
            }
        }
        __syncthreads();
    }

    if (flags & 4) {
        // ---- fused final-dot epilogue ----
        float part[4][2];
#pragma unroll
        for (int i = 0; i < 4; i++) { part[i][0] = 0.f; part[i][1] = 0.f; }
#pragma unroll
        for (int i = 0; i < 4; i++) {
#pragma unroll
            for (int j = 0; j < 4; j++) {
                int col = bn + wn * 32 + j * 8 + ((lane & 3) << 1);
                if (col >= Nd) continue;
                float2 w = *(const float2*)(wc + col);
                float bx = 0.f, by = 0.f;
                if (bias) { float2 b = *(const float2*)(bias + col); bx = b.x; by = b.y; }
#pragma unroll
                for (int h = 0; h < 2; h++) {
                    float v0 = acc[i][j][2 * h + 0] + bx;
                    float v1 = acc[i][j][2 * h + 1] + by;
                    part[i][h] += v0 * w.x + v1 * w.y;
                }
            }
        }
#pragma unroll
        for (int i = 0; i < 4; i++)
#pragma unroll
            for (int h = 0; h < 2; h++) {
                float p = part[i][h];
                p += __shfl_xor_sync(0xFFFFFFFFu, p, 1);
                p += __shfl_xor_sync(0xFFFFFFFFu, p, 2);
                if ((lane & 3) == 0) {
                    int row = bm + wm * 64 + i * 16 + h * 8 + (lane >> 2);
                    atomicAdd(&g_segout[g_segid[row]], p);
                }
            }
    } else if (flags & (8 | 32)) {
        // ---- raw bf16 hi/lo output (stride Nd) + fused stats ----
        float csum0[4], csum1[4], sq = 0.f;
        float gs = 0.f, gss = 0.f;
#pragma unroll
        for (int j = 0; j < 4; j++) { csum0[j] = 0.f; csum1[j] = 0.f; }
#pragma unroll
        for (int i = 0; i < 4; i++) {
            int row0 = bm + wm * 64 + i * 16 + (lane >> 2);
#pragma unroll
            for (int j = 0; j < 4; j++) {
                int col = bn + wn * 32 + j * 8 + ((lane & 3) << 1);
                if (col >= Nd) continue;
                float2 b = *(const float2*)(bias + col);
#pragma unroll
                for (int h = 0; h < 2; h++) {
                    int row = row0 + h * 8;
                    float v0 = acc[i][j][2 * h + 0] + b.x;
                    float v1 = acc[i][j][2 * h + 1] + b.y;
                    if (flags & 2) {
                        v0 = (v0 >= 0.f) ? v0 : 0.01f * v0;
                        v1 = (v1 >= 0.f) ? v1 : 0.01f * v1;
                    }
                    if (flags & 8) {
                        csum0[j] += v0; csum1[j] += v1;
                        sq += v0 * v0 + v1 * v1;
                    }
                    if (flags & 16) {
                        gs += v0 + v1;
                        gss += v0 * v0 + v1 * v1;
                    }
                    __nv_bfloat16 h0, l0, h1, l1;
                    split_bf16(v0, h0, l0);
                    split_bf16(v1, h1, l1);
                    size_t o = (size_t)row * Nd + col;
                    *(__nv_bfloat162*)(Rhi + o) = __nv_bfloat162{h0, h1};
                    *(__nv_bfloat162*)(Rlo + o) = __nv_bfloat162{l0, l1};
                }
            }
        }
        if (flags & 8) {
#pragma unroll
            for (int j = 0; j < 4; j++) {
#pragma unroll
                for (int o = 4; o < 32; o <<= 1) {
                    csum0[j] += __shfl_xor_sync(0xFFFFFFFFu, csum0[j], o);
                    csum1[j] += __shfl_xor_sync(0xFFFFFFFFu, csum1[j], o);
                }
            }
            if (lane < 4) {
#pragma unroll
                for (int j = 0; j < 4; j++) {
                    int col = bn + wn * 32 + j * 8 + lane * 2;
                    atomicAdd(&g_colsum[col], csum0[j]);
                    atomicAdd(&g_colsum[col + 1], csum1[j]);
                }
            }
#pragma unroll
            for (int o = 1; o < 32; o <<= 1) sq += __shfl_xor_sync(0xFFFFFFFFu, sq, o);
            __shared__ float sqsh[8];
            if (lane == 0) sqsh[wid] = sq;
            __syncthreads();
            if (tid == 0) {
                float t = 0.f;
#pragma unroll
                for (int w = 0; w < 8; w++) t += sqsh[w];
                atomicAdd(&g_scalar[0], t);
            }
        }
        if (flags & 16) {
#pragma unroll
            for (int o = 1; o < 32; o <<= 1) {
                gs += __shfl_xor_sync(0xFFFFFFFFu, gs, o);
                gss += __shfl_xor_sync(0xFFFFFFFFu, gss, o);
            }
            if (lane == 0) {
                int seg = bm >> 8;
                atomicAdd(&g_glnsum[seg], gs);
                atomicAdd(&g_glnss[seg], gss);
            }
        }
    } else {
        // ---- fp32 epilogue; optional leaky + gln stats ----
        float gs = 0.f, gss = 0.f;
#pragma unroll
        for (int i = 0; i < 4; i++) {
            int row0 = bm + wm * 64 + i * 16 + (lane >> 2);
#pragma unroll
            for (int j = 0; j < 4; j++) {
                int col = bn + wn * 32 + j * 8 + ((lane & 3) << 1);
                if (col >= Nd) continue;
                float bx = 0.f, by = 0.f;
                if (bias) { float2 b = *(const float2*)(bias + col); bx = b.x; by = b.y; }
#pragma unroll
                for (int h = 0; h < 2; h++) {
                    int row = row0 + h * 8;
                    float v0 = acc[i][j][2 * h + 0] + bx;
                    float v1 = acc[i][j][2 * h + 1] + by;
                    if (flags & 2) {
                        v0 = (v0 >= 0.f) ? v0 : 0.01f * v0;
                        v1 = (v1 >= 0.f) ? v1 : 0.01f * v1;
                    }
                    if (flags & 16) {
                        gs += v0 + v1;
                        gss += v0 * v0 + v1 * v1;
                    }
                    *(float2*)(C + (size_t)row * Nd + col) = make_float2(v0, v1);
                }
            }
        }
        if (flags & 16) {
#pragma unroll
            for (int o = 1; o < 32; o <<= 1) {
                gs += __shfl_xor_sync(0xFFFFFFFFu, gs, o);
                gss += __shfl_xor_sync(0xFFFFFFFFu, gss, o);
            }
            if (lane == 0) {
                int seg = bm >> 8;
                atomicAdd(&g_glnsum[seg], gs);
                atomicAdd(&g_glnss[seg], gss);
            }
        }
    }
}

// ---------------- graph-wise LN finalize (self-zeroing) ----------------
__global__ void k_glnfin(int D) {
    int t = threadIdx.x;
    if (t < NS) {
        float cnt = 256.f * (float)D;
        float mean = g_glnsum[t] / cnt;
        float var = g_glnss[t] / cnt - mean * mean;
        g_glnstat[2 * t] = mean;
        g_glnstat[2 * t + 1] = rsqrtf(var + 1e-5f);
        g_glnsum[t] = 0.f;
        g_glnss[t] = 0.f;
    }
}
// gln apply + bf16 split (used for MLP1 output only)
__global__ void k_glnapply_cvt(const float* __restrict__ x, const float* __restrict__ gamma,
                               const float* __restrict__ beta, int D, int Kpad,
                               int colOff, int strideK,
                               __nv_bfloat16* __restrict__ hi, __nv_bfloat16* __restrict__ lo) {
    int r = blockIdx.x;
    int f = blockIdx.y * blockDim.x + threadIdx.x;
    if (f >= Kpad) return;
    float v = 0.f;
    if (f < D) {
        int s = g_segid[r];
        v = (x[(size_t)r * D + f] - g_glnstat[2 * s]) * g_glnstat[2 * s + 1] * gamma[f] + beta[f];
    }
    __nv_bfloat16 h, l;
    split_bf16(v, h, l);
    size_t o = (size_t)r * strideK + colOff + f;
    hi[o] = h; lo[o] = l;
}

// ---------------- PairNorm finalize (self-zeroing) ----------------
__global__ void k_pnfin() {
    int t = threadIdx.x;
    float m = g_colsum[t] / (float)NND;
    g_pnmean[t] = m;
    __shared__ float sh[512];
    sh[t] = m * m;
    __syncthreads();
    for (int o = 256; o > 0; o >>= 1) {
        if (t < o) sh[t] += sh[t + o];
        __syncthreads();
    }
    if (t == 0) {
        float var = g_scalar[0] / (float)NND - sh[0];
        g_scalar[1] = 1.f / (1e-5f + sqrtf(fmaxf(var, 0.f)));
        g_scalar[0] = 0.f;
    }
    g_colsum[t] = 0.f;
}

__global__ void k_out(float* __restrict__ out, const float* __restrict__ bc) {
    int t = threadIdx.x;
    if (t < NS) out[t] = g_segout[t] + bc[0];
}

// ---------------- host orchestration ----------------
static __nv_bfloat16 *h_ahi, *h_alo, *h_whi, *h_wlo, *h_rhi, *h_rlo;

static inline void run_gemm(const float* bias, float* C, const float* wc,
                            int Kp, int Nd, int Ndp, int flags) {
    dim3 grid(Ndp / 128, NND / 128);
    k_mmagemm<<<grid, 256, GSMEM>>>(h_ahi, h_alo, h_whi, h_wlo, bias, C,
                                    h_rhi, h_rlo, wc, Kp, Nd, flags);
}

extern "C" void kernel_launch(void* const* d_in, const int* in_sizes, int n_in,
                              void* d_out, int out_size) {
    const float* nf   = (const float*)d_in[0];
    const float* ncf  = (const float*)d_in[1];
    const float* emb  = (const float*)d_in[2];
    const float* w1   = (const float*)d_in[3];
    const float* b1   = (const float*)d_in[4];
    const float* g1   = (const float*)d_in[5];
    const float* be1  = (const float*)d_in[6];
    const float* w2   = (const float*)d_in[7];
    const float* b2   = (const float*)d_in[8];
    const float* g2   = (const float*)d_in[9];
    const float* be2  = (const float*)d_in[10];
    const float* wl1  = (const float*)d_in[11];
    const float* bl1  = (const float*)d_in[12];
    const float* wr1  = (const float*)d_in[13];
    const float* wl2  = (const float*)d_in[14];
    const float* bl2  = (const float*)d_in[15];
    const float* wr2  = (const float*)d_in[16];
    const float* wl3  = (const float*)d_in[17];
    const float* bl3  = (const float*)d_in[18];
    const float* wr3  = (const float*)d_in[19];
    const float* wc   = (const float*)d_in[20];
    const float* bc   = (const float*)d_in[21];
    const int* ops    = (const int*)d_in[22];
    const int* edges  = (const int*)d_in[23];
    const int* sep    = (const int*)d_in[24];
    float* out        = (float*)d_out;

    const int* src = edges;
    const int* dst = edges + NE;

    cudaFuncSetAttribute(k_mmagemm, cudaFuncAttributeMaxDynamicSharedMemorySize, GSMEM);

    void *p_x1, *p_ahi, *p_alo, *p_whi, *p_wlo, *p_rhi, *p_rlo;
    cudaGetSymbolAddress(&p_x1, g_x1);
    cudaGetSymbolAddress(&p_ahi, g_ahi);
    cudaGetSymbolAddress(&p_alo, g_alo);
    cudaGetSymbolAddress(&p_whi, g_whi);
    cudaGetSymbolAddress(&p_wlo, g_wlo);
    cudaGetSymbolAddress(&p_rhi, g_rhi);
    cudaGetSymbolAddress(&p_rlo, g_rlo);
    float* d_x1 = (float*)p_x1;
    h_ahi = (__nv_bfloat16*)p_ahi;
    h_alo = (__nv_bfloat16*)p_alo;
    h_whi = (__nv_bfloat16*)p_whi;
    h_wlo = (__nv_bfloat16*)p_wlo;
    h_rhi = (__nv_bfloat16*)p_rhi;
    h_rlo = (__nv_bfloat16*)p_rlo;

    // ---- prep: segids, CSR build (scan also zeroes stats), input concat ----
    k_segid<<<(NND + 255) / 256, 256>>>(sep);
    k_hist<<<(NE + 255) / 256, 256>>>(dst);
    k_scan<<<1, 1024>>>();
    k_fillcsr<<<(NE + 255) / 256, 256>>>(src, dst);
    k_concat_cvt<<<(NND * 192 + 255) / 256, 256>>>(nf, ncf, emb, ops, h_ahi, h_alo);

    // ---- MLP layer 1: K=192, Nd=380 (Ndp 384), fused gln-stats ----
    k_cvtW<<<(384 * 192 + 255) / 256, 256>>>(w1, h_whi, h_wlo, D_X, D_0, 384, 192);
    run_gemm(b1, d_x1, nullptr, 192, D_X, 384, /*leaky+glnstats*/2 | 16);
    k_glnfin<<<1, NS>>>(D_X);
    k_glnapply_cvt<<<dim3(NND, 2), 256>>>(d_x1, g1, be1, D_X, 384, 0, 384, h_ahi, h_alo);

    // ---- MLP layer 2: K=384, Nd=256 -> raw bf16 + fused gln-stats ----
    k_cvtW<<<(256 * 384 + 255) / 256, 256>>>(w2, h_whi, h_wlo, D_GIN, D_X, 256, 384);
    run_gemm(b2, nullptr, nullptr, 384, D_GIN, 256, /*raw+leaky+gln*/32 | 2 | 16);
    k_glnfin<<<1, NS>>>(D_GIN);

    // ---- SAGE layer 1: gln fused into gather; combined K=512 -> raw bf16 + pn-stats ----
    {
        k_cvtWpair<<<(512 * 512 + 255) / 256, 256>>>(wl1, wr1, h_whi, h_wlo, D_GIN);
        k_gather_gln<<<NND / 8, 256>>>(h_rhi, h_rlo, g2, be2, h_ahi, h_alo);
        run_gemm(bl1, nullptr, nullptr, 512, D_GH, 512, /*raw+pnstats*/8);
        k_pnfin<<<1, 512>>>();
    }

    // ---- SAGE layer 2: pn fused into gather; combined K=1024 -> raw bf16 + pn-stats ----
    {
        k_cvtWpair<<<(512 * 1024 + 255) / 256, 256>>>(wl2, wr2, h_whi, h_wlo, D_GH);
        k_gather_pn<<<NND / 8, 256>>>(h_rhi, h_rlo, h_ahi, h_alo);
        run_gemm(bl2, nullptr, nullptr, 1024, D_GH, 512, 8);
        k_pnfin<<<1, 512>>>();
    }

    // ---- SAGE layer 3: pn fused into gather; combined K=1024, fused final dot ----
    {
        k_cvtWpair<<<(512 * 1024 + 255) / 256, 256>>>(wl3, wr3, h_whi, h_wlo, D_GH);
        k_gather_pn<<<NND / 8, 256>>>(h_rhi, h_rlo, h_ahi, h_alo);
        run_gemm(bl3, nullptr, wc, 1024, D_GH, 512, /*fused dot*/4);
    }

    k_out<<<1, NS>>>(out, bc);
}

// round 15
// speedup vs baseline: 1.0080x; 1.0080x over previous
#include <cuda_runtime.h>
#include <cuda_bf16.h>
#include <math.h>
#include <stdint.h>

// ---------------- problem constants ----------------
#define NND 32768
#define NE  262144
#define NS  128
#define D_0 190
#define D_X 380
#define D_GIN 256
#define D_GH 512

// weight buffer layout (elements)
#define WOFF_W1   0
#define WOFF_W2   73728
#define WOFF_S1   172032
#define WOFF_S2   434176
#define WOFF_S3   958464
#define WTOTAL    1482752

// ---------------- device scratch (static, no allocation) ----------------
__device__ __align__(128) float g_x1[(size_t)NND * D_X];
__device__ __align__(128) float g_xb[(size_t)NND * D_GIN];
__device__ __align__(128) __nv_bfloat16 g_ahi[(size_t)NND * 1024];
__device__ __align__(128) __nv_bfloat16 g_alo[(size_t)NND * 1024];
__device__ __align__(128) __nv_bfloat16 g_rhi[(size_t)NND * D_GH];
__device__ __align__(128) __nv_bfloat16 g_rlo[(size_t)NND * D_GH];
__device__ __align__(128) __nv_bfloat16 g_whi[WTOTAL];
__device__ __align__(128) __nv_bfloat16 g_wlo[WTOTAL];
__device__ float g_invdeg[NND];
__device__ int   g_segid[NND];
__device__ int   g_deg[NND];
__device__ int   g_rowstart[NND + 1];
__device__ int   g_cursor[NND];
__device__ int   g_csrsrc[NE];
__device__ float g_glnstat[NS * 2];
__device__ float g_glnsum[NS];
__device__ float g_glnss[NS];
__device__ float g_colsum[D_GH];
__device__ float g_pnmean[D_GH];
__device__ float g_scalar[2];
__device__ float g_segout[NS];

// ---------------- PTX helpers (compute_103-safe) ----------------
__device__ __forceinline__ uint32_t smem_u32(const void* p) {
    uint32_t a;
    asm("{ .reg .u64 t; cvta.to.shared.u64 t, %1; cvt.u32.u64 %0, t; }" : "=r"(a) : "l"(p));
    return a;
}
__device__ __forceinline__ void cpasync16(uint32_t dst, const void* src) {
    asm volatile("cp.async.cg.shared.global [%0], [%1], 16;" :: "r"(dst), "l"(src) : "memory");
}
__device__ __forceinline__ void ldm_x4(uint32_t* r, uint32_t addr) {
    asm volatile("ldmatrix.sync.aligned.m8n8.x4.shared.b16 {%0,%1,%2,%3},[%4];"
                 : "=r"(r[0]), "=r"(r[1]), "=r"(r[2]), "=r"(r[3]) : "r"(addr));
}
__device__ __forceinline__ void ldm_x2(uint32_t* r, uint32_t addr) {
    asm volatile("ldmatrix.sync.aligned.m8n8.x2.shared.b16 {%0,%1},[%2];"
                 : "=r"(r[0]), "=r"(r[1]) : "r"(addr));
}
__device__ __forceinline__ void mma_bf16(float* d, const uint32_t* a, const uint32_t* b) {
    asm volatile(
        "mma.sync.aligned.m16n8k16.row.col.f32.bf16.bf16.f32 "
        "{%0,%1,%2,%3}, {%4,%5,%6,%7}, {%8,%9}, {%0,%1,%2,%3};"
        : "+f"(d[0]), "+f"(d[1]), "+f"(d[2]), "+f"(d[3])
        : "r"(a[0]), "r"(a[1]), "r"(a[2]), "r"(a[3]), "r"(b[0]), "r"(b[1]));
}
__device__ __forceinline__ void split_bf16(float v, __nv_bfloat16& h, __nv_bfloat16& l) {
    h = __float2bfloat16(v);
    l = __float2bfloat16(v - __bfloat162float(h));
}

// ---------------- small utility kernels ----------------
__global__ void k_segid(const int* __restrict__ sep) {
    int i = blockIdx.x * blockDim.x + threadIdx.x;
    if (i >= NND) return;
    int lo = 0, hi = NS;
    while (lo < hi) { int mid = (lo + hi) >> 1; if (sep[mid] <= i) lo = mid + 1; else hi = mid; }
    g_segid[i] = lo;
    g_deg[i] = 0;
}
__global__ void k_hist(const int* __restrict__ dst) {
    int e = blockIdx.x * blockDim.x + threadIdx.x;
    if (e < NE) atomicAdd(&g_deg[dst[e]], 1);
}
// one-block scan over degrees; also zeroes all stat accumulators
__global__ void __launch_bounds__(1024) k_scan() {
    __shared__ int sh[1024];
    int t = threadIdx.x;
    if (t < D_GH) g_colsum[t] = 0.f;
    if (t < 2) g_scalar[t] = 0.f;
    if (t < NS) { g_segout[t] = 0.f; g_glnsum[t] = 0.f; g_glnss[t] = 0.f; }
    int base = t * 32;
    int loc[32];
    int s = 0;
#pragma unroll
    for (int i = 0; i < 32; i++) { loc[i] = s; s += g_deg[base + i]; }
    sh[t] = s;
    __syncthreads();
    for (int o = 1; o < 1024; o <<= 1) {
        int v = (t >= o) ? sh[t - o] : 0;
        __syncthreads();
        sh[t] += v;
        __syncthreads();
    }
    int start = (t == 0) ? 0 : sh[t - 1];
#pragma unroll
    for (int i = 0; i < 32; i++) {
        int n = base + i;
        int st = start + loc[i];
        g_rowstart[n] = st;
        g_cursor[n] = st;
        int d = g_deg[n];
        g_invdeg[n] = 1.f / (float)((d > 1) ? d : 1);
    }
    if (t == 1023) g_rowstart[NND] = sh[1023];
}
__global__ void k_fillcsr(const int* __restrict__ src, const int* __restrict__ dst) {
    int e = blockIdx.x * blockDim.x + threadIdx.x;
    if (e >= NE) return;
    int d = dst[e];
    int pos = atomicAdd(&g_cursor[d], 1);
    g_csrsrc[pos] = src[e];
}
__global__ void k_concat_cvt(const float* __restrict__ nf, const float* __restrict__ ncf,
                             const float* __restrict__ emb, const int* __restrict__ ops,
                             __nv_bfloat16* __restrict__ hi, __nv_bfloat16* __restrict__ lo) {
    size_t i = (size_t)blockIdx.x * blockDim.x + threadIdx.x;
    if (i >= (size_t)NND * 192) return;
    int r = (int)(i / 192);
    int c = (int)(i - (size_t)r * 192);
    float v = 0.f;
    if (c < 90)       v = nf[(size_t)r * 90 + c];
    else if (c < 126) v = ncf[(size_t)r * 36 + (c - 90)];
    else if (c < 190) v = emb[(size_t)ops[r] * 64 + (c - 126)];
    __nv_bfloat16 h, l;
    split_bf16(v, h, l);
    hi[i] = h; lo[i] = l;
}
__global__ void k_cvtW(const float* __restrict__ W, __nv_bfloat16* __restrict__ hi,
                       __nv_bfloat16* __restrict__ lo, int Nd, int K, int Ndp, int Kp) {
    int idx = blockIdx.x * blockDim.x + threadIdx.x;
    if (idx >= Ndp * Kp) return;
    int n = idx / Kp, k = idx - n * Kp;
    float v = (n < Nd && k < K) ? W[(size_t)n * K + k] : 0.f;
    __nv_bfloat16 h, l;
    split_bf16(v, h, l);
    hi[idx] = h; lo[idx] = l;
}
__global__ void k_cvtWpair(const float* __restrict__ wl, const float* __restrict__ wr,
                           __nv_bfloat16* __restrict__ hi, __nv_bfloat16* __restrict__ lo, int K1) {
    int Kt = 2 * K1;
    int idx = blockIdx.x * blockDim.x + threadIdx.x;
    if (idx >= 512 * Kt) return;
    int n = idx / Kt, k = idx - n * Kt;
    float v = (k < K1) ? wl[(size_t)n * K1 + k] : wr[(size_t)n * K1 + (k - K1)];
    __nv_bfloat16 h, l;
    split_bf16(v, h, l);
    hi[idx] = h; lo[idx] = l;
}

// ---------------- CSR gather (plain, bf16 hi/lo input at cols [D,2D)) ----------------
template <int D>
__global__ void __launch_bounds__(256)
k_gather_bf(__nv_bfloat16* __restrict__ hi, __nv_bfloat16* __restrict__ lo) {
    const int warp = (blockIdx.x * blockDim.x + threadIdx.x) >> 5;
    if (warp >= NND) return;
    const int lane = threadIdx.x & 31;
    const int s0 = g_rowstart[warp];
    const int s1 = g_rowstart[warp + 1];
    constexpr int SW = D / 256;
    float acc[SW][8];
#pragma unroll
    for (int w = 0; w < SW; w++)
#pragma unroll
        for (int q = 0; q < 8; q++) acc[w][q] = 0.f;

    for (int e = s0; e < s1; e++) {
        int s = g_csrsrc[e];
        size_t base = (size_t)s * (2 * D) + D + (size_t)lane * 8;
#pragma unroll
        for (int w = 0; w < SW; w++) {
            uint4 h4 = *(const uint4*)(hi + base + w * 256);
            uint4 l4 = *(const uint4*)(lo + base + w * 256);
            const __nv_bfloat162* hp = (const __nv_bfloat162*)&h4;
            const __nv_bfloat162* lp = (const __nv_bfloat162*)&l4;
#pragma unroll
            for (int q = 0; q < 4; q++) {
                float2 hf = __bfloat1622float2(hp[q]);
                float2 lf = __bfloat1622float2(lp[q]);
                acc[w][2 * q + 0] += hf.x + lf.x;
                acc[w][2 * q + 1] += hf.y + lf.y;
            }
        }
    }
    const float inv = g_invdeg[warp];
    size_t ob = (size_t)warp * (2 * D) + (size_t)lane * 8;
#pragma unroll
    for (int w = 0; w < SW; w++) {
        __nv_bfloat162 hv[4], lv[4];
#pragma unroll
        for (int q = 0; q < 4; q++) {
            __nv_bfloat16 h0, l0, h1, l1;
            split_bf16(acc[w][2 * q + 0] * inv, h0, l0);
            split_bf16(acc[w][2 * q + 1] * inv, h1, l1);
            hv[q] = __nv_bfloat162{h0, h1};
            lv[q] = __nv_bfloat162{l0, l1};
        }
        *(uint4*)(hi + ob + w * 256) = *(const uint4*)hv;
        *(uint4*)(lo + ob + w * 256) = *(const uint4*)lv;
    }
}

// ---------------- CSR gather with fused PairNorm+ReLU (D=512) ----------------
__global__ void __launch_bounds__(256)
k_gather_pn(const __nv_bfloat16* __restrict__ rhi, const __nv_bfloat16* __restrict__ rlo,
            __nv_bfloat16* __restrict__ hi, __nv_bfloat16* __restrict__ lo) {
    const int warp = (blockIdx.x * blockDim.x + threadIdx.x) >> 5;
    if (warp >= NND) return;
    const int lane = threadIdx.x & 31;
    const float sc = g_scalar[1];
    float mean[2][8];
#pragma unroll
    for (int w = 0; w < 2; w++)
#pragma unroll
        for (int q = 0; q < 8; q++) mean[w][q] = g_pnmean[w * 256 + lane * 8 + q];

    {
        size_t sb = (size_t)warp * 512 + (size_t)lane * 8;
        size_t ob = (size_t)warp * 1024 + 512 + (size_t)lane * 8;
#pragma unroll
        for (int w = 0; w < 2; w++) {
            uint4 h4 = *(const uint4*)(rhi + sb + w * 256);
            uint4 l4 = *(const uint4*)(rlo + sb + w * 256);
            const __nv_bfloat162* hp = (const __nv_bfloat162*)&h4;
            const __nv_bfloat162* lp = (const __nv_bfloat162*)&l4;
            __nv_bfloat162 hv[4], lv[4];
#pragma unroll
            for (int q = 0; q < 4; q++) {
                float2 hf = __bfloat1622float2(hp[q]);
                float2 lf = __bfloat1622float2(lp[q]);
                float v0 = fmaxf((hf.x + lf.x - mean[w][2 * q + 0]) * sc, 0.f);
                float v1 = fmaxf((hf.y + lf.y - mean[w][2 * q + 1]) * sc, 0.f);
                __nv_bfloat16 h0, l0, h1, l1;
                split_bf16(v0, h0, l0);
                split_bf16(v1, h1, l1);
                hv[q] = __nv_bfloat162{h0, h1};
                lv[q] = __nv_bfloat162{l0, l1};
            }
            *(uint4*)(hi + ob + w * 256) = *(const uint4*)hv;
            *(uint4*)(lo + ob + w * 256) = *(const uint4*)lv;
        }
    }

    const int s0 = g_rowstart[warp];
    const int s1 = g_rowstart[warp + 1];
    float acc[2][8];
#pragma unroll
    for (int w = 0; w < 2; w++)
#pragma unroll
        for (int q = 0; q < 8; q++) acc[w][q] = 0.f;
    for (int e = s0; e < s1; e++) {
        int s = g_csrsrc[e];
        size_t base = (size_t)s * 512 + (size_t)lane * 8;
#pragma unroll
        for (int w = 0; w < 2; w++) {
            uint4 h4 = *(const uint4*)(rhi + base + w * 256);
            uint4 l4 = *(const uint4*)(rlo + base + w * 256);
            const __nv_bfloat162* hp = (const __nv_bfloat162*)&h4;
            const __nv_bfloat162* lp = (const __nv_bfloat162*)&l4;
#pragma unroll
            for (int q = 0; q < 4; q++) {
                float2 hf = __bfloat1622float2(hp[q]);
                float2 lf = __bfloat1622float2(lp[q]);
                acc[w][2 * q + 0] += fmaxf((hf.x + lf.x - mean[w][2 * q + 0]) * sc, 0.f);
                acc[w][2 * q + 1] += fmaxf((hf.y + lf.y - mean[w][2 * q + 1]) * sc, 0.f);
            }
        }
    }
    const float inv = g_invdeg[warp];
    size_t ob = (size_t)warp * 1024 + (size_t)lane * 8;
#pragma unroll
    for (int w = 0; w < 2; w++) {
        __nv_bfloat162 hv[4], lv[4];
#pragma unroll
        for (int q = 0; q < 4; q++) {
            __nv_bfloat16 h0, l0, h1, l1;
            split_bf16(acc[w][2 * q + 0] * inv, h0, l0);
            split_bf16(acc[w][2 * q + 1] * inv, h1, l1);
            hv[q] = __nv_bfloat162{h0, h1};
            lv[q] = __nv_bfloat162{l0, l1};
        }
        *(uint4*)(hi + ob + w * 256) = *(const uint4*)hv;
        *(uint4*)(lo + ob + w * 256) = *(const uint4*)lv;
    }
}

// ---------------- mma.sync bf16x3 GEMM (BK=32, 2 CTAs/SM) ----------------
// flags: 2 = leaky-relu, 4 = fused segment-dot, 8 = raw-bf16 out + pairnorm stats,
//        16 = gln stats (seg = bm>>8)
#define MAT_BYTES 10240
#define STG_BYTES 40960
#define GSMEM (2 * STG_BYTES)

__global__ void __launch_bounds__(256, 2)
k_mmagemm(const __nv_bfloat16* __restrict__ Ahi, const __nv_bfloat16* __restrict__ Alo,
          const __nv_bfloat16* __restrict__ Whi, const __nv_bfloat16* __restrict__ Wlo,
          const float* __restrict__ bias, float* __restrict__ C,
          __nv_bfloat16* __restrict__ Rhi, __nv_bfloat16* __restrict__ Rlo,
          const float* __restrict__ wc, int Kp, int Nd, int flags)
{
    extern __shared__ char smc[];
    const uint32_t sbase = smem_u32(smc);
    const int tid = threadIdx.x;
    const int lane = tid & 31;
    const int wid = tid >> 5;
    const int wm = wid & 1;
    const int wn = wid >> 1;
    const int bm = blockIdx.y * 128;
    const int bn = blockIdx.x * 128;

    const __nv_bfloat16* gsrc[4] = {Ahi, Alo, Whi, Wlo};
    const int rbase[4] = {bm, bm, bn, bn};
    const int nc = Kp >> 5;

    const uint32_t abyte = (uint32_t)((wm * 64 + (lane & 15)) * 80 + ((lane >> 4) & 1) * 16);
    const uint32_t bbyte = (uint32_t)((wn * 32 + (lane & 7)) * 80 + ((lane >> 3) & 1) * 16);

    float acc[4][4][4];
#pragma unroll
    for (int i = 0; i < 4; i++)
#pragma unroll
        for (int j = 0; j < 4; j++)
#pragma unroll
            for (int q = 0; q < 4; q++) acc[i][j][q] = 0.f;

    auto load_chunk = [&](int c) {
        const int k0 = c * 32;
        const uint32_t sdst0 = sbase + (uint32_t)(c & 1) * STG_BYTES;
#pragma unroll
        for (int t = 0; t < 8; t++) {
            int idx = tid + t * 256;
            int mat = idx >> 9;
            int u = idx & 511;
            int row = u >> 2, seg = u & 3;
            uint32_t dst = sdst0 + (uint32_t)mat * MAT_BYTES + (uint32_t)(row * 80 + seg * 16);
            const __nv_bfloat16* src = gsrc[mat] + (size_t)(rbase[mat] + row) * Kp + k0 + seg * 8;
            cpasync16(dst, src);
        }
        asm volatile("cp.async.commit_group;" ::: "memory");
    };

    load_chunk(0);

    for (int c = 0; c < nc; c++) {
        if (c + 1 < nc) {
            load_chunk(c + 1);
            asm volatile("cp.async.wait_group 1;" ::: "memory");
        } else {
            asm volatile("cp.async.wait_group 0;" ::: "memory");
        }
        __syncthreads();

        const uint32_t st = sbase + (uint32_t)(c & 1) * STG_BYTES;
        const uint32_t aHI = st + abyte;
        const uint32_t aLO = st + MAT_BYTES + abyte;
        const uint32_t wHI = st + 2 * MAT_BYTES + bbyte;
        const uint32_t wLO = st + 3 * MAT_BYTES + bbyte;

#pragma unroll
        for (int ks = 0; ks < 2; ks++) {
            uint32_t wh[4][2], wl[4][2];
#pragma unroll
            for (int j = 0; j < 4; j++) {
                ldm_x2(wh[j], wHI + (uint32_t)(j * 640 + ks * 32));
                ldm_x2(wl[j], wLO + (uint32_t)(j * 640 + ks * 32));
            }
#pragma unroll
            for (int i = 0; i < 4; i++) {
                uint32_t ah[4], al[4];
                ldm_x4(ah, aHI + (uint32_t)(i * 1280 + ks * 32));
                ldm_x4(al, aLO + (uint32_t)(i * 1280 + ks * 32));
#pragma unroll
                for (int j = 0; j < 4; j++) {
                    mma_bf16(acc[i][j], ah, wh[j]);
                    mma_bf16(acc[i][j], ah, wl[j]);
                    mma_bf16(acc[i][j], al, wh[j]);
                }
            }
        }
        __syncthreads();
    }

    if (flags & 4) {
        float part[4][2];
#pragma unroll
        for (int i = 0; i < 4; i++) { part[i][0] = 0.f; part[i][1] = 0.f; }
#pragma unroll
        for (int i = 0; i < 4; i++) {
#pragma unroll
            for (int j = 0; j < 4; j++) {
                int col = bn + wn * 32 + j * 8 + ((lane & 3) << 1);
                if (col >= Nd) continue;
                float2 w = *(const float2*)(wc + col);
                float bx = 0.f, by = 0.f;
                if (bias) { float2 b = *(const float2*)(bias + col); bx = b.x; by = b.y; }
#pragma unroll
                for (int h = 0; h < 2; h++) {
                    float v0 = acc[i][j][2 * h + 0] + bx;
                    float v1 = acc[i][j][2 * h + 1] + by;
                    part[i][h] += v0 * w.x + v1 * w.y;
                }
            }
        }
#pragma unroll
        for (int i = 0; i < 4; i++)
#pragma unroll
            for (int h = 0; h < 2; h++) {
                float p = part[i][h];
                p += __shfl_xor_sync(0xFFFFFFFFu, p, 1);
                p += __shfl_xor_sync(0xFFFFFFFFu, p, 2);
                if ((lane & 3) == 0) {
                    int row = bm + wm * 64 + i * 16 + h * 8 + (lane >> 2);
                    atomicAdd(&g_segout[g_segid[row]], p);
                }
            }
    } else if (flags & 8) {
        // ---- raw bf16 hi/lo output + fused pairnorm stats (Nd == 512) ----
        float csum0[4], csum1[4], sq = 0.f;
#pragma unroll
        for (int j = 0; j < 4; j++) { csum0[j] = 0.f; csum1[j] = 0.f; }
#pragma unroll
        for (int i = 0; i < 4; i++) {
            int row0 = bm + wm * 64 + i * 16 + (lane >> 2);
#pragma unroll
            for (int j = 0; j < 4; j++) {
                int col = bn + wn * 32 + j * 8 + ((lane & 3) << 1);
                float2 b = *(const float2*)(bias + col);
#pragma unroll
                for (int h = 0; h < 2; h++) {
                    int row = row0 + h * 8;
                    float v0 = acc[i][j][2 * h + 0] + b.x;
                    float v1 = acc[i][j][2 * h + 1] + b.y;
                    csum0[j] += v0; csum1[j] += v1;
                    sq += v0 * v0 + v1 * v1;
                    __nv_bfloat16 h0, l0, h1, l1;
                    split_bf16(v0, h0, l0);
                    split_bf16(v1, h1, l1);
                    size_t o = (size_t)row * 512 + col;
                    *(__nv_bfloat162*)(Rhi + o) = __nv_bfloat162{h0, h1};
                    *(__nv_bfloat162*)(Rlo + o) = __nv_bfloat162{l0, l1};
                }
            }
        }
#pragma unroll
        for (int j = 0; j < 4; j++) {
#pragma unroll
            for (int o = 4; o < 32; o <<= 1) {
                csum0[j] += __shfl_xor_sync(0xFFFFFFFFu, csum0[j], o);
                csum1[j] += __shfl_xor_sync(0xFFFFFFFFu, csum1[j], o);
            }
        }
        if (lane < 4) {
#pragma unroll
            for (int j = 0; j < 4; j++) {
                int col = bn + wn * 32 + j * 8 + lane * 2;
                atomicAdd(&g_colsum[col], csum0[j]);
                atomicAdd(&g_colsum[col + 1], csum1[j]);
            }
        }
#pragma unroll
        for (int o = 1; o < 32; o <<= 1) sq += __shfl_xor_sync(0xFFFFFFFFu, sq, o);
        __shared__ float sqsh[8];
        if (lane == 0) sqsh[wid] = sq;
        __syncthreads();
        if (tid == 0) {
            float t = 0.f;
#pragma unroll
            for (int w = 0; w < 8; w++) t += sqsh[w];
            atomicAdd(&g_scalar[0], t);
        }
    } else {
        // ---- fp32 epilogue; optional leaky + gln stats ----
        float gs = 0.f, gss = 0.f;
#pragma unroll
        for (int i = 0; i < 4; i++) {
            int row0 = bm + wm * 64 + i * 16 + (lane >> 2);
#pragma unroll
            for (int j = 0; j < 4; j++) {
                int col = bn + wn * 32 + j * 8 + ((lane & 3) << 1);
                if (col >= Nd) continue;
                float bx = 0.f, by = 0.f;
                if (bias) { float2 b = *(const float2*)(bias + col); bx = b.x; by = b.y; }
#pragma unroll
                for (int h = 0; h < 2; h++) {
                    int row = row0 + h * 8;
                    float v0 = acc[i][j][2 * h + 0] + bx;
                    float v1 = acc[i][j][2 * h + 1] + by;
                    if (flags & 2) {
                        v0 = (v0 >= 0.f) ? v0 : 0.01f * v0;
                        v1 = (v1 >= 0.f) ? v1 : 0.01f * v1;
                    }
                    if (flags & 16) {
                        gs += v0 + v1;
                        gss += v0 * v0 + v1 * v1;
                    }
                    *(float2*)(C + (size_t)row * Nd + col) = make_float2(v0, v1);
                }
            }
        }
        if (flags & 16) {
#pragma unroll
            for (int o = 1; o < 32; o <<= 1) {
                gs += __shfl_xor_sync(0xFFFFFFFFu, gs, o);
                gss += __shfl_xor_sync(0xFFFFFFFFu, gss, o);
            }
            if (lane == 0) {
                int seg = bm >> 8;
                atomicAdd(&g_glnsum[seg], gs);
                atomicAdd(&g_glnss[seg], gss);
            }
        }
    }
}

// ---------------- graph-wise LN finalize (self-zeroing) ----------------
__global__ void k_glnfin(int D) {
    int t = threadIdx.x;
    if (t < NS) {
        float cnt = 256.f * (float)D;
        float mean = g_glnsum[t] / cnt;
        float var = g_glnss[t] / cnt - mean * mean;
        g_glnstat[2 * t] = mean;
        g_glnstat[2 * t + 1] = rsqrtf(var + 1e-5f);
        g_glnsum[t] = 0.f;
        g_glnss[t] = 0.f;
    }
}
__global__ void k_glnapply_cvt(const float* __restrict__ x, const float* __restrict__ gamma,
                               const float* __restrict__ beta, int D, int Kpad,
                               int colOff, int strideK,
                               __nv_bfloat16* __restrict__ hi, __nv_bfloat16* __restrict__ lo) {
    int r = blockIdx.x;
    int f = blockIdx.y * blockDim.x + threadIdx.x;
    if (f >= Kpad) return;
    float v = 0.f;
    if (f < D) {
        int s = g_segid[r];
        v = (x[(size_t)r * D + f] - g_glnstat[2 * s]) * g_glnstat[2 * s + 1] * gamma[f] + beta[f];
    }
    __nv_bfloat16 h, l;
    split_bf16(v, h, l);
    size_t o = (size_t)r * strideK + colOff + f;
    hi[o] = h; lo[o] = l;
}

// ---------------- PairNorm finalize (self-zeroing) ----------------
__global__ void k_pnfin() {
    int t = threadIdx.x;
    float m = g_colsum[t] / (float)NND;
    g_pnmean[t] = m;
    __shared__ float sh[512];
    sh[t] = m * m;
    __syncthreads();
    for (int o = 256; o > 0; o >>= 1) {
        if (t < o) sh[t] += sh[t + o];
        __syncthreads();
    }
    if (t == 0) {
        float var = g_scalar[0] / (float)NND - sh[0];
        g_scalar[1] = 1.f / (1e-5f + sqrtf(fmaxf(var, 0.f)));
        g_scalar[0] = 0.f;
    }
    g_colsum[t] = 0.f;
}

__global__ void k_out(float* __restrict__ out, const float* __restrict__ bc) {
    int t = threadIdx.x;
    if (t < NS) out[t] = g_segout[t] + bc[0];
}

// ---------------- host orchestration ----------------
static __nv_bfloat16 *h_ahi, *h_alo, *h_whi, *h_wlo, *h_rhi, *h_rlo;

static inline void run_gemm(const __nv_bfloat16* Whi, const __nv_bfloat16* Wlo,
                            const float* bias, float* C, const float* wc,
                            int Kp, int Nd, int Ndp, int flags) {
    dim3 grid(Ndp / 128, NND / 128);
    k_mmagemm<<<grid, 256, GSMEM>>>(h_ahi, h_alo, Whi, Wlo, bias, C,
                                    h_rhi, h_rlo, wc, Kp, Nd, flags);
}

extern "C" void kernel_launch(void* const* d_in, const int* in_sizes, int n_in,
                              void* d_out, int out_size) {
    const float* nf   = (const float*)d_in[0];
    const float* ncf  = (const float*)d_in[1];
    const float* emb  = (const float*)d_in[2];
    const float* w1   = (const float*)d_in[3];
    const float* b1   = (const float*)d_in[4];
    const float* g1   = (const float*)d_in[5];
    const float* be1  = (const float*)d_in[6];
    const float* w2   = (const float*)d_in[7];
    const float* b2   = (const float*)d_in[8];
    const float* g2   = (const float*)d_in[9];
    const float* be2  = (const float*)d_in[10];
    const float* wl1  = (const float*)d_in[11];
    const float* bl1  = (const float*)d_in[12];
    const float* wr1  = (const float*)d_in[13];
    const float* wl2  = (const float*)d_in[14];
    const float* bl2  = (const float*)d_in[15];
    const float* wr2  = (const float*)d_in[16];
    const float* wl3  = (const float*)d_in[17];
    const float* bl3  = (const float*)d_in[18];
    const float* wr3  = (const float*)d_in[19];
    const float* wc   = (const float*)d_in[20];
    const float* bc   = (const float*)d_in[21];
    const int* ops    = (const int*)d_in[22];
    const int* edges  = (const int*)d_in[23];
    const int* sep    = (const int*)d_in[24];
    float* out        = (float*)d_out;

    const int* src = edges;
    const int* dst = edges + NE;

    cudaFuncSetAttribute(k_mmagemm, cudaFuncAttributeMaxDynamicSharedMemorySize, GSMEM);

    void *p_x1, *p_xb, *p_ahi, *p_alo, *p_whi, *p_wlo, *p_rhi, *p_rlo;
    cudaGetSymbolAddress(&p_x1, g_x1);
    cudaGetSymbolAddress(&p_xb, g_xb);
    cudaGetSymbolAddress(&p_ahi, g_ahi);
    cudaGetSymbolAddress(&p_alo, g_alo);
    cudaGetSymbolAddress(&p_whi, g_whi);
    cudaGetSymbolAddress(&p_wlo, g_wlo);
    cudaGetSymbolAddress(&p_rhi, g_rhi);
    cudaGetSymbolAddress(&p_rlo, g_rlo);
    float* d_x1 = (float*)p_x1;
    float* d_xb = (float*)p_xb;
    h_ahi = (__nv_bfloat16*)p_ahi;
    h_alo = (__nv_bfloat16*)p_alo;
    h_whi = (__nv_bfloat16*)p_whi;
    h_wlo = (__nv_bfloat16*)p_wlo;
    h_rhi = (__nv_bfloat16*)p_rhi;
    h_rlo = (__nv_bfloat16*)p_rlo;

    // persistent side stream + events (created once; identical work per call)
    static cudaStream_t s_side = nullptr;
    static cudaEvent_t s_evFork = nullptr, s_evJoin = nullptr;
    if (s_side == nullptr) {
        cudaStreamCreateWithFlags(&s_side, cudaStreamNonBlocking);
        cudaEventCreateWithFlags(&s_evFork, cudaEventDisableTiming);
        cudaEventCreateWithFlags(&s_evJoin, cudaEventDisableTiming);
    }

    // ---- fork: all weight conversions on side stream (depend only on inputs) ----
    cudaEventRecord(s_evFork, 0);
    cudaStreamWaitEvent(s_side, s_evFork, 0);
    k_cvtW<<<(384 * 192 + 255) / 256, 256, 0, s_side>>>(w1, h_whi + WOFF_W1, h_wlo + WOFF_W1, D_X, D_0, 384, 192);
    k_cvtW<<<(256 * 384 + 255) / 256, 256, 0, s_side>>>(w2, h_whi + WOFF_W2, h_wlo + WOFF_W2, D_GIN, D_X, 256, 384);
    k_cvtWpair<<<(512 * 512 + 255) / 256, 256, 0, s_side>>>(wl1, wr1, h_whi + WOFF_S1, h_wlo + WOFF_S1, D_GIN);
    k_cvtWpair<<<(512 * 1024 + 255) / 256, 256, 0, s_side>>>(wl2, wr2, h_whi + WOFF_S2, h_wlo + WOFF_S2, D_GH);
    k_cvtWpair<<<(512 * 1024 + 255) / 256, 256, 0, s_side>>>(wl3, wr3, h_whi + WOFF_S3, h_wlo + WOFF_S3, D_GH);
    cudaEventRecord(s_evJoin, s_side);

    // ---- main stream: segids, CSR build (scan also zeroes stats), input concat ----
    k_segid<<<(NND + 255) / 256, 256>>>(sep);
    k_hist<<<(NE + 255) / 256, 256>>>(dst);
    k_scan<<<1, 1024>>>();
    k_fillcsr<<<(NE + 255) / 256, 256>>>(src, dst);
    k_concat_cvt<<<(NND * 192 + 255) / 256, 256>>>(nf, ncf, emb, ops, h_ahi, h_alo);

    // ---- join: weights ready ----
    cudaStreamWaitEvent(0, s_evJoin, 0);

    // ---- MLP layer 1: K=192, Nd=380 (Ndp 384), fused gln-stats ----
    run_gemm(h_whi + WOFF_W1, h_wlo + WOFF_W1, b1, d_x1, nullptr, 192, D_X, 384, 2 | 16);
    k_glnfin<<<1, NS>>>(D_X);
    k_glnapply_cvt<<<dim3(NND, 2), 256>>>(d_x1, g1, be1, D_X, 384, 0, 384, h_ahi, h_alo);

    // ---- MLP layer 2: K=384, Nd=256, fused gln-stats ----
    run_gemm(h_whi + WOFF_W2, h_wlo + WOFF_W2, b2, d_xb, nullptr, 384, D_GIN, 256, 2 | 16);
    k_glnfin<<<1, NS>>>(D_GIN);
    k_glnapply_cvt<<<dim3(NND, 1), 256>>>(d_xb, g2, be2, D_GIN, 256, 256, 512, h_ahi, h_alo);

    // ---- SAGE layer 1: combined K=512 -> raw bf16 + pn-stats ----
    k_gather_bf<D_GIN><<<NND / 8, 256>>>(h_ahi, h_alo);
    run_gemm(h_whi + WOFF_S1, h_wlo + WOFF_S1, bl1, nullptr, nullptr, 512, D_GH, 512, 8);
    k_pnfin<<<1, 512>>>();

    // ---- SAGE layer 2: pn fused into gather; combined K=1024 -> raw bf16 + pn-stats ----
    k_gather_pn<<<NND / 8, 256>>>(h_rhi, h_rlo, h_ahi, h_alo);
    run_gemm(h_whi + WOFF_S2, h_wlo + WOFF_S2, bl2, nullptr, nullptr, 1024, D_GH, 512, 8);
    k_pnfin<<<1, 512>>>();

    // ---- SAGE layer 3: pn fused into gather; combined K=1024, fused final dot ----
    k_gather_pn<<<NND / 8, 256>>>(h_rhi, h_rlo, h_ahi, h_alo);
    run_gemm(h_whi + WOFF_S3, h_wlo + WOFF_S3, bl3, nullptr, wc, 1024, D_GH, 512, 4);

    k_out<<<1, NS>>>(out, bc);
}

// round 17
// speedup vs baseline: 1.0436x; 1.0353x over previous
#include <cuda_runtime.h>
#include <cuda_bf16.h>
#include <math.h>
#include <stdint.h>

// ---------------- problem constants ----------------
#define NND 32768
#define NE  262144
#define NS  128
#define D_0 190
#define D_X 380
#define D_GIN 256
#define D_GH 512

// weight buffer layout (elements)
#define WOFF_W1   0
#define WOFF_W2   73728
#define WOFF_S1   172032
#define WOFF_S2   434176
#define WOFF_S3   958464
#define WTOTAL    1482752

// ---------------- device scratch (static, no allocation) ----------------
__device__ __align__(128) float g_x1[(size_t)NND * D_X];
__device__ __align__(128) float g_xb[(size_t)NND * D_GIN];
__device__ __align__(128) __nv_bfloat16 g_ahi[(size_t)NND * 1024];
__device__ __align__(128) __nv_bfloat16 g_alo[(size_t)NND * 1024];
__device__ __align__(128) __nv_bfloat16 g_rhi[(size_t)NND * D_GH];
__device__ __align__(128) __nv_bfloat16 g_rlo[(size_t)NND * D_GH];
__device__ __align__(128) __nv_bfloat16 g_whi[WTOTAL];
__device__ __align__(128) __nv_bfloat16 g_wlo[WTOTAL];
__device__ float g_invdeg[NND];
__device__ int   g_segid[NND];
__device__ int   g_deg[NND];
__device__ int   g_rowstart[NND + 1];
__device__ int   g_cursor[NND];
__device__ int   g_csrsrc[NE];
__device__ float g_glnsum[2 * NS];
__device__ float g_glnss[2 * NS];
__device__ float g_colsum[D_GH];
__device__ float g_pnmean[D_GH];
__device__ float g_scalar[2];
__device__ float g_segout[NS];

// ---------------- PTX helpers (compute_103-safe) ----------------
__device__ __forceinline__ uint32_t smem_u32(const void* p) {
    uint32_t a;
    asm("{ .reg .u64 t; cvta.to.shared.u64 t, %1; cvt.u32.u64 %0, t; }" : "=r"(a) : "l"(p));
    return a;
}
__device__ __forceinline__ void cpasync16(uint32_t dst, const void* src) {
    asm volatile("cp.async.cg.shared.global [%0], [%1], 16;" :: "r"(dst), "l"(src) : "memory");
}
__device__ __forceinline__ void ldm_x4(uint32_t* r, uint32_t addr) {
    asm volatile("ldmatrix.sync.aligned.m8n8.x4.shared.b16 {%0,%1,%2,%3},[%4];"
                 : "=r"(r[0]), "=r"(r[1]), "=r"(r[2]), "=r"(r[3]) : "r"(addr));
}
__device__ __forceinline__ void ldm_x2(uint32_t* r, uint32_t addr) {
    asm volatile("ldmatrix.sync.aligned.m8n8.x2.shared.b16 {%0,%1},[%2];"
                 : "=r"(r[0]), "=r"(r[1]) : "r"(addr));
}
__device__ __forceinline__ void mma_bf16(float* d, const uint32_t* a, const uint32_t* b) {
    asm volatile(
        "mma.sync.aligned.m16n8k16.row.col.f32.bf16.bf16.f32 "
        "{%0,%1,%2,%3}, {%4,%5,%6,%7}, {%8,%9}, {%0,%1,%2,%3};"
        : "+f"(d[0]), "+f"(d[1]), "+f"(d[2]), "+f"(d[3])
        : "r"(a[0]), "r"(a[1]), "r"(a[2]), "r"(a[3]), "r"(b[0]), "r"(b[1]));
}
__device__ __forceinline__ void split_bf16(float v, __nv_bfloat16& h, __nv_bfloat16& l) {
    h = __float2bfloat16(v);
    l = __float2bfloat16(v - __bfloat162float(h));
}

// ---------------- small utility kernels ----------------
// segid + zero all accumulators (deg, stats)
__global__ void k_segid(const int* __restrict__ sep) {
    int i = blockIdx.x * blockDim.x + threadIdx.x;
    if (i >= NND) return;
    int lo = 0, hi = NS;
    while (lo < hi) { int mid = (lo + hi) >> 1; if (sep[mid] <= i) lo = mid + 1; else hi = mid; }
    g_segid[i] = lo;
    g_deg[i] = 0;
    if (i < D_GH) g_colsum[i] = 0.f;
    if (i < 2) g_scalar[i] = 0.f;
    if (i < NS) g_segout[i] = 0.f;
    if (i < 2 * NS) { g_glnsum[i] = 0.f; g_glnss[i] = 0.f; }
}
__global__ void k_hist(const int* __restrict__ dst) {
    int e = blockIdx.x * blockDim.x + threadIdx.x;
    if (e < NE) atomicAdd(&g_deg[dst[e]], 1);
}
__global__ void __launch_bounds__(1024) k_scan() {
    __shared__ int sh[1024];
    int t = threadIdx.x;
    int base = t * 32;
    int loc[32];
    int s = 0;
#pragma unroll
    for (int i = 0; i < 32; i++) { loc[i] = s; s += g_deg[base + i]; }
    sh[t] = s;
    __syncthreads();
    for (int o = 1; o < 1024; o <<= 1) {
        int v = (t >= o) ? sh[t - o] : 0;
        __syncthreads();
        sh[t] += v;
        __syncthreads();
    }
    int start = (t == 0) ? 0 : sh[t - 1];
#pragma unroll
    for (int i = 0; i < 32; i++) {
        int n = base + i;
        int st = start + loc[i];
        g_rowstart[n] = st;
        g_cursor[n] = st;
        int d = g_deg[n];
        g_invdeg[n] = 1.f / (float)((d > 1) ? d : 1);
    }
    if (t == 1023) g_rowstart[NND] = sh[1023];
}
__global__ void k_fillcsr(const int* __restrict__ src, const int* __restrict__ dst) {
    int e = blockIdx.x * blockDim.x + threadIdx.x;
    if (e >= NE) return;
    int d = dst[e];
    int pos = atomicAdd(&g_cursor[d], 1);
    g_csrsrc[pos] = src[e];
}
__global__ void k_concat_cvt(const float* __restrict__ nf, const float* __restrict__ ncf,
                             const float* __restrict__ emb, const int* __restrict__ ops,
                             __nv_bfloat16* __restrict__ hi, __nv_bfloat16* __restrict__ lo) {
    size_t i = (size_t)blockIdx.x * blockDim.x + threadIdx.x;
    if (i >= (size_t)NND * 192) return;
    int r = (int)(i / 192);
    int c = (int)(i - (size_t)r * 192);
    float v = 0.f;
    if (c < 90)       v = nf[(size_t)r * 90 + c];
    else if (c < 126) v = ncf[(size_t)r * 36 + (c - 90)];
    else if (c < 190) v = emb[(size_t)ops[r] * 64 + (c - 126)];
    __nv_bfloat16 h, l;
    split_bf16(v, h, l);
    hi[i] = h; lo[i] = l;
}
__global__ void k_cvtW(const float* __restrict__ W, __nv_bfloat16* __restrict__ hi,
                       __nv_bfloat16* __restrict__ lo, int Nd, int K, int Ndp, int Kp) {
    int idx = blockIdx.x * blockDim.x + threadIdx.x;
    if (idx >= Ndp * Kp) return;
    int n = idx / Kp, k = idx - n * Kp;
    float v = (n < Nd && k < K) ? W[(size_t)n * K + k] : 0.f;
    __nv_bfloat16 h, l;
    split_bf16(v, h, l);
    hi[idx] = h; lo[idx] = l;
}
__global__ void k_cvtWpair(const float* __restrict__ wl, const float* __restrict__ wr,
                           __nv_bfloat16* __restrict__ hi, __nv_bfloat16* __restrict__ lo, int K1) {
    int Kt = 2 * K1;
    int idx = blockIdx.x * blockDim.x + threadIdx.x;
    if (idx >= 512 * Kt) return;
    int n = idx / Kt, k = idx - n * Kt;
    float v = (k < K1) ? wl[(size_t)n * K1 + k] : wr[(size_t)n * K1 + (k - K1)];
    __nv_bfloat16 h, l;
    split_bf16(v, h, l);
    hi[idx] = h; lo[idx] = l;
}

// ---------------- CSR gather (plain, bf16 hi/lo input at cols [D,2D)) ----------------
template <int D>
__global__ void __launch_bounds__(256)
k_gather_bf(__nv_bfloat16* __restrict__ hi, __nv_bfloat16* __restrict__ lo) {
    const int warp = (blockIdx.x * blockDim.x + threadIdx.x) >> 5;
    if (warp >= NND) return;
    const int lane = threadIdx.x & 31;
    const int s0 = g_rowstart[warp];
    const int s1 = g_rowstart[warp + 1];
    constexpr int SW = D / 256;
    float acc[SW][8];
#pragma unroll
    for (int w = 0; w < SW; w++)
#pragma unroll
        for (int q = 0; q < 8; q++) acc[w][q] = 0.f;

    for (int e = s0; e < s1; e++) {
        int s = g_csrsrc[e];
        size_t base = (size_t)s * (2 * D) + D + (size_t)lane * 8;
#pragma unroll
        for (int w = 0; w < SW; w++) {
            uint4 h4 = *(const uint4*)(hi + base + w * 256);
            uint4 l4 = *(const uint4*)(lo + base + w * 256);
            const __nv_bfloat162* hp = (const __nv_bfloat162*)&h4;
            const __nv_bfloat162* lp = (const __nv_bfloat162*)&l4;
#pragma unroll
            for (int q = 0; q < 4; q++) {
                float2 hf = __bfloat1622float2(hp[q]);
                float2 lf = __bfloat1622float2(lp[q]);
                acc[w][2 * q + 0] += hf.x + lf.x;
                acc[w][2 * q + 1] += hf.y + lf.y;
            }
        }
    }
    const float inv = g_invdeg[warp];
    size_t ob = (size_t)warp * (2 * D) + (size_t)lane * 8;
#pragma unroll
    for (int w = 0; w < SW; w++) {
        __nv_bfloat162 hv[4], lv[4];
#pragma unroll
        for (int q = 0; q < 4; q++) {
            __nv_bfloat16 h0, l0, h1, l1;
            split_bf16(acc[w][2 * q + 0] * inv, h0, l0);
            split_bf16(acc[w][2 * q + 1] * inv, h1, l1);
            hv[q] = __nv_bfloat162{h0, h1};
            lv[q] = __nv_bfloat162{l0, l1};
        }
        *(uint4*)(hi + ob + w * 256) = *(const uint4*)hv;
        *(uint4*)(lo + ob + w * 256) = *(const uint4*)lv;
    }
}

// ---------------- CSR gather with fused PairNorm+ReLU (D=512) ----------------
__global__ void __launch_bounds__(256)
k_gather_pn(const __nv_bfloat16* __restrict__ rhi, const __nv_bfloat16* __restrict__ rlo,
            __nv_bfloat16* __restrict__ hi, __nv_bfloat16* __restrict__ lo) {
    const int warp = (blockIdx.x * blockDim.x + threadIdx.x) >> 5;
    if (warp >= NND) return;
    const int lane = threadIdx.x & 31;
    const float sc = g_scalar[1];
    float mean[2][8];
#pragma unroll
    for (int w = 0; w < 2; w++)
#pragma unroll
        for (int q = 0; q < 8; q++) mean[w][q] = g_pnmean[w * 256 + lane * 8 + q];

    {
        size_t sb = (size_t)warp * 512 + (size_t)lane * 8;
        size_t ob = (size_t)warp * 1024 + 512 + (size_t)lane * 8;
#pragma unroll
        for (int w = 0; w < 2; w++) {
            uint4 h4 = *(const uint4*)(rhi + sb + w * 256);
            uint4 l4 = *(const uint4*)(rlo + sb + w * 256);
            const __nv_bfloat162* hp = (const __nv_bfloat162*)&h4;
            const __nv_bfloat162* lp = (const __nv_bfloat162*)&l4;
            __nv_bfloat162 hv[4], lv[4];
#pragma unroll
            for (int q = 0; q < 4; q++) {
                float2 hf = __bfloat1622float2(hp[q]);
                float2 lf = __bfloat1622float2(lp[q]);
                float v0 = fmaxf((hf.x + lf.x - mean[w][2 * q + 0]) * sc, 0.f);
                float v1 = fmaxf((hf.y + lf.y - mean[w][2 * q + 1]) * sc, 0.f);
                __nv_bfloat16 h0, l0, h1, l1;
                split_bf16(v0, h0, l0);
                split_bf16(v1, h1, l1);
                hv[q] = __nv_bfloat162{h0, h1};
                lv[q] = __nv_bfloat162{l0, l1};
            }
            *(uint4*)(hi + ob + w * 256) = *(const uint4*)hv;
            *(uint4*)(lo + ob + w * 256) = *(const uint4*)lv;
        }
    }

    const int s0 = g_rowstart[warp];
    const int s1 = g_rowstart[warp + 1];
    float acc[2][8];
#pragma unroll
    for (int w = 0; w < 2; w++)
#pragma unroll
        for (int q = 0; q < 8; q++) acc[w][q] = 0.f;
    for (int e = s0; e < s1; e++) {
        int s = g_csrsrc[e];
        size_t base = (size_t)s * 512 + (size_t)lane * 8;
#pragma unroll
        for (int w = 0; w < 2; w++) {
            uint4 h4 = *(const uint4*)(rhi + base + w * 256);
            uint4 l4 = *(const uint4*)(rlo + base + w * 256);
            const __nv_bfloat162* hp = (const __nv_bfloat162*)&h4;
            const __nv_bfloat162* lp = (const __nv_bfloat162*)&l4;
#pragma unroll
            for (int q = 0; q < 4; q++) {
                float2 hf = __bfloat1622float2(hp[q]);
                float2 lf = __bfloat1622float2(lp[q]);
                acc[w][2 * q + 0] += fmaxf((hf.x + lf.x - mean[w][2 * q + 0]) * sc, 0.f);
                acc[w][2 * q + 1] += fmaxf((hf.y + lf.y - mean[w][2 * q + 1]) * sc, 0.f);
            }
        }
    }
    const float inv = g_invdeg[warp];
    size_t ob = (size_t)warp * 1024 + (size_t)lane * 8;
#pragma unroll
    for (int w = 0; w < 2; w++) {
        __nv_bfloat162 hv[4], lv[4];
#pragma unroll
        for (int q = 0; q < 4; q++) {
            __nv_bfloat16 h0, l0, h1, l1;
            split_bf16(acc[w][2 * q + 0] * inv, h0, l0);
            split_bf16(acc[w][2 * q + 1] * inv, h1, l1);
            hv[q] = __nv_bfloat162{h0, h1};
            lv[q] = __nv_bfloat162{l0, l1};
        }
        *(uint4*)(hi + ob + w * 256) = *(const uint4*)hv;
        *(uint4*)(lo + ob + w * 256) = *(const uint4*)lv;
    }
}

// ---------------- mma.sync bf16x3 GEMM (BK=32, 2 CTAs/SM) ----------------
// flags: 2 = leaky-relu, 4 = fused segment-dot, 8 = raw-bf16 out + pairnorm stats,
//        16 = gln stats (seg = bm>>8), 64 = gln stat slot 1
#define MAT_BYTES 10240
#define STG_BYTES 40960
#define GSMEM (2 * STG_BYTES)

__global__ void __launch_bounds__(256, 2)
k_mmagemm(const __nv_bfloat16* __restrict__ Ahi, const __nv_bfloat16* __restrict__ Alo,
          const __nv_bfloat16* __restrict__ Whi, const __nv_bfloat16* __restrict__ Wlo,
          const float* __restrict__ bias, float* __restrict__ C,
          __nv_bfloat16* __restrict__ Rhi, __nv_bfloat16* __restrict__ Rlo,
          const float* __restrict__ wc, int Kp, int Nd, int flags)
{
    extern __shared__ char smc[];
    const uint32_t sbase = smem_u32(smc);
    const int tid = threadIdx.x;
    const int lane = tid & 31;
    const int wid = tid >> 5;
    const int wm = wid & 1;
    const int wn = wid >> 1;
    const int bm = blockIdx.y * 128;
    const int bn = blockIdx.x * 128;

    const __nv_bfloat16* gsrc[4] = {Ahi, Alo, Whi, Wlo};
    const int rbase[4] = {bm, bm, bn, bn};
    const int nc = Kp >> 5;

    const uint32_t abyte = (uint32_t)((wm * 64 + (lane & 15)) * 80 + ((lane >> 4) & 1) * 16);
    const uint32_t bbyte = (uint32_t)((wn * 32 + (lane & 7)) * 80 + ((lane >> 3) & 1) * 16);

    float acc[4][4][4];
#pragma unroll
    for (int i = 0; i < 4; i++)
#pragma unroll
        for (int j = 0; j < 4; j++)
#pragma unroll
            for (int q = 0; q < 4; q++) acc[i][j][q] = 0.f;

    auto load_chunk = [&](int c) {
        const int k0 = c * 32;
        const uint32_t sdst0 = sbase + (uint32_t)(c & 1) * STG_BYTES;
#pragma unroll
        for (int t = 0; t < 8; t++) {
            int idx = tid + t * 256;
            int mat = idx >> 9;
            int u = idx & 511;
            int row = u >> 2, seg = u & 3;
            uint32_t dst = sdst0 + (uint32_t)mat * MAT_BYTES + (uint32_t)(row * 80 + seg * 16);
            const __nv_bfloat16* src = gsrc[mat] + (size_t)(rbase[mat] + row) * Kp + k0 + seg * 8;
            cpasync16(dst, src);
        }
        asm volatile("cp.async.commit_group;" ::: "memory");
    };

    load_chunk(0);

    for (int c = 0; c < nc; c++) {
        if (c + 1 < nc) {
            load_chunk(c + 1);
            asm volatile("cp.async.wait_group 1;" ::: "memory");
        } else {
            asm volatile("cp.async.wait_group 0;" ::: "memory");
        }
        __syncthreads();

        const uint32_t st = sbase + (uint32_t)(c & 1) * STG_BYTES;
        const uint32_t aHI = st + abyte;
        const uint32_t aLO = st + MAT_BYTES + abyte;
        const uint32_t wHI = st + 2 * MAT_BYTES + bbyte;
        const uint32_t wLO = st + 3 * MAT_BYTES + bbyte;

#pragma unroll
        for (int ks = 0; ks < 2; ks++) {
            uint32_t wh[4][2], wl[4][2];
#pragma unroll
            for (int j = 0; j < 4; j++) {
                ldm_x2(wh[j], wHI + (uint32_t)(j * 640 + ks * 32));
                ldm_x2(wl[j], wLO + (uint32_t)(j * 640 + ks * 32));
            }
#pragma unroll
            for (int i = 0; i < 4; i++) {
                uint32_t ah[4], al[4];
                ldm_x4(ah, aHI + (uint32_t)(i * 1280 + ks * 32));
                ldm_x4(al, aLO + (uint32_t)(i * 1280 + ks * 32));
#pragma unroll
                for (int j = 0; j < 4; j++) {
                    mma_bf16(acc[i][j], ah, wh[j]);
                    mma_bf16(acc[i][j], ah, wl[j]);
                    mma_bf16(acc[i][j], al, wh[j]);
                }
            }
        }
        __syncthreads();
    }

    if (flags & 4) {
        float part[4][2];
#pragma unroll
        for (int i = 0; i < 4; i++) { part[i][0] = 0.f; part[i][1] = 0.f; }
#pragma unroll
        for (int i = 0; i < 4; i++) {
#pragma unroll
            for (int j = 0; j < 4; j++) {
                int col = bn + wn * 32 + j * 8 + ((lane & 3) << 1);
                if (col >= Nd) continue;
                float2 w = *(const float2*)(wc + col);
                float bx = 0.f, by = 0.f;
                if (bias) { float2 b = *(const float2*)(bias + col); bx = b.x; by = b.y; }
#pragma unroll
                for (int h = 0; h < 2; h++) {
                    float v0 = acc[i][j][2 * h + 0] + bx;
                    float v1 = acc[i][j][2 * h + 1] + by;
                    part[i][h] += v0 * w.x + v1 * w.y;
                }
            }
        }
#pragma unroll
        for (int i = 0; i < 4; i++)
#pragma unroll
            for (int h = 0; h < 2; h++) {
                float p = part[i][h];
                p += __shfl_xor_sync(0xFFFFFFFFu, p, 1);
                p += __shfl_xor_sync(0xFFFFFFFFu, p, 2);
                if ((lane & 3) == 0) {
                    int row = bm + wm * 64 + i * 16 + h * 8 + (lane >> 2);
                    atomicAdd(&g_segout[g_segid[row]], p);
                }
            }
    } else if (flags & 8) {
        // ---- raw bf16 hi/lo output + fused pairnorm stats (Nd == 512) ----
        float csum0[4], csum1[4], sq = 0.f;
#pragma unroll
        for (int j = 0; j < 4; j++) { csum0[j] = 0.f; csum1[j] = 0.f; }
#pragma unroll
        for (int i = 0; i < 4; i++) {
            int row0 = bm + wm * 64 + i * 16 + (lane >> 2);
#pragma unroll
            for (int j = 0; j < 4; j++) {
                int col = bn + wn * 32 + j * 8 + ((lane & 3) << 1);
                float2 b = *(const float2*)(bias + col);
#pragma unroll
                for (int h = 0; h < 2; h++) {
                    int row = row0 + h * 8;
                    float v0 = acc[i][j][2 * h + 0] + b.x;
                    float v1 = acc[i][j][2 * h + 1] + b.y;
                    csum0[j] += v0; csum1[j] += v1;
                    sq += v0 * v0 + v1 * v1;
                    __nv_bfloat16 h0, l0, h1, l1;
                    split_bf16(v0, h0, l0);
                    split_bf16(v1, h1, l1);
                    size_t o = (size_t)row * 512 + col;
                    *(__nv_bfloat162*)(Rhi + o) = __nv_bfloat162{h0, h1};
                    *(__nv_bfloat162*)(Rlo + o) = __nv_bfloat162{l0, l1};
                }
            }
        }
#pragma unroll
        for (int j = 0; j < 4; j++) {
#pragma unroll
            for (int o = 4; o < 32; o <<= 1) {
                csum0[j] += __shfl_xor_sync(0xFFFFFFFFu, csum0[j], o);
                csum1[j] += __shfl_xor_sync(0xFFFFFFFFu, csum1[j], o);
            }
        }
        if (lane < 4) {
#pragma unroll
            for (int j = 0; j < 4; j++) {
                int col = bn + wn * 32 + j * 8 + lane * 2;
                atomicAdd(&g_colsum[col], csum0[j]);
                atomicAdd(&g_colsum[col + 1], csum1[j]);
            }
        }
#pragma unroll
        for (int o = 1; o < 32; o <<= 1) sq += __shfl_xor_sync(0xFFFFFFFFu, sq, o);
        __shared__ float sqsh[8];
        if (lane == 0) sqsh[wid] = sq;
        __syncthreads();
        if (tid == 0) {
            float t = 0.f;
#pragma unroll
            for (int w = 0; w < 8; w++) t += sqsh[w];
            atomicAdd(&g_scalar[0], t);
        }
    } else {
        // ---- fp32 epilogue; optional leaky + gln stats ----
        float gs = 0.f, gss = 0.f;
#pragma unroll
        for (int i = 0; i < 4; i++) {
            int row0 = bm + wm * 64 + i * 16 + (lane >> 2);
#pragma unroll
            for (int j = 0; j < 4; j++) {
                int col = bn + wn * 32 + j * 8 + ((lane & 3) << 1);
                if (col >= Nd) continue;
                float bx = 0.f, by = 0.f;
                if (bias) { float2 b = *(const float2*)(bias + col); bx = b.x; by = b.y; }
#pragma unroll
                for (int h = 0; h < 2; h++) {
                    int row = row0 + h * 8;
                    float v0 = acc[i][j][2 * h + 0] + bx;
                    float v1 = acc[i][j][2 * h + 1] + by;
                    if (flags & 2) {
                        v0 = (v0 >= 0.f) ? v0 : 0.01f * v0;
                        v1 = (v1 >= 0.f) ? v1 : 0.01f * v1;
                    }
                    if (flags & 16) {
                        gs += v0 + v1;
                        gss += v0 * v0 + v1 * v1;
                    }
                    *(float2*)(C + (size_t)row * Nd + col) = make_float2(v0, v1);
                }
            }
        }
        if (flags & 16) {
#pragma unroll
            for (int o = 1; o < 32; o <<= 1) {
                gs += __shfl_xor_sync(0xFFFFFFFFu, gs, o);
                gss += __shfl_xor_sync(0xFFFFFFFFu, gss, o);
            }
            if (lane == 0) {
                int seg = (bm >> 8) + ((flags & 64) ? NS : 0);
                atomicAdd(&g_glnsum[seg], gs);
                atomicAdd(&g_glnss[seg], gss);
            }
        }
    }
}

// ---------------- gln apply with inline finalize + bf16 split ----------------
__global__ void k_glnapply_cvt(const float* __restrict__ x, const float* __restrict__ gamma,
                               const float* __restrict__ beta, int D, int Kpad,
                               int colOff, int strideK, int slot,
                               __nv_bfloat16* __restrict__ hi, __nv_bfloat16* __restrict__ lo) {
    int r = blockIdx.x;
    int f = blockIdx.y * blockDim.x + threadIdx.x;
    if (f >= Kpad) return;
    float v = 0.f;
    if (f < D) {
        int s = g_segid[r] + slot;
        float cnt = 256.f * (float)D;
        float mean = g_glnsum[s] / cnt;
        float var = g_glnss[s] / cnt - mean * mean;
        float is = rsqrtf(var + 1e-5f);
        v = (x[(size_t)r * D + f] - mean) * is * gamma[f] + beta[f];
    }
    __nv_bfloat16 h, l;
    split_bf16(v, h, l);
    size_t o = (size_t)r * strideK + colOff + f;
    hi[o] = h; lo[o] = l;
}

// ---------------- PairNorm finalize (self-zeroing) ----------------
__global__ void k_pnfin() {
    int t = threadIdx.x;
    float m = g_colsum[t] / (float)NND;
    g_pnmean[t] = m;
    __shared__ float sh[512];
    sh[t] = m * m;
    __syncthreads();
    for (int o = 256; o > 0; o >>= 1) {
        if (t < o) sh[t] += sh[t + o];
        __syncthreads();
    }
    if (t == 0) {
        float var = g_scalar[0] / (float)NND - sh[0];
        g_scalar[1] = 1.f / (1e-5f + sqrtf(fmaxf(var, 0.f)));
        g_scalar[0] = 0.f;
    }
    g_colsum[t] = 0.f;
}

__global__ void k_out(float* __restrict__ out, const float* __restrict__ bc) {
    int t = threadIdx.x;
    if (t < NS) out[t] = g_segout[t] + bc[0];
}

// ---------------- host orchestration ----------------
static __nv_bfloat16 *h_ahi, *h_alo, *h_whi, *h_wlo, *h_rhi, *h_rlo;

static inline void run_gemm(const __nv_bfloat16* Whi, const __nv_bfloat16* Wlo,
                            const float* bias, float* C, const float* wc,
                            int Kp, int Nd, int Ndp, int flags) {
    dim3 grid(Ndp / 128, NND / 128);
    k_mmagemm<<<grid, 256, GSMEM>>>(h_ahi, h_alo, Whi, Wlo, bias, C,
                                    h_rhi, h_rlo, wc, Kp, Nd, flags);
}

extern "C" void kernel_launch(void* const* d_in, const int* in_sizes, int n_in,
                              void* d_out, int out_size) {
    const float* nf   = (const float*)d_in[0];
    const float* ncf  = (const float*)d_in[1];
    const float* emb  = (const float*)d_in[2];
    const float* w1   = (const float*)d_in[3];
    const float* b1   = (const float*)d_in[4];
    const float* g1   = (const float*)d_in[5];
    const float* be1  = (const float*)d_in[6];
    const float* w2   = (const float*)d_in[7];
    const float* b2   = (const float*)d_in[8];
    const float* g2   = (const float*)d_in[9];
    const float* be2  = (const float*)d_in[10];
    const float* wl1  = (const float*)d_in[11];
    const float* bl1  = (const float*)d_in[12];
    const float* wr1  = (const float*)d_in[13];
    const float* wl2  = (const float*)d_in[14];
    const float* bl2  = (const float*)d_in[15];
    const float* wr2  = (const float*)d_in[16];
    const float* wl3  = (const float*)d_in[17];
    const float* bl3  = (const float*)d_in[18];
    const float* wr3  = (const float*)d_in[19];
    const float* wc   = (const float*)d_in[20];
    const float* bc   = (const float*)d_in[21];
    const int* ops    = (const int*)d_in[22];
    const int* edges  = (const int*)d_in[23];
    const int* sep    = (const int*)d_in[24];
    float* out        = (float*)d_out;

    const int* src = edges;
    const int* dst = edges + NE;

    cudaFuncSetAttribute(k_mmagemm, cudaFuncAttributeMaxDynamicSharedMemorySize, GSMEM);

    void *p_x1, *p_xb, *p_ahi, *p_alo, *p_whi, *p_wlo, *p_rhi, *p_rlo;
    cudaGetSymbolAddress(&p_x1, g_x1);
    cudaGetSymbolAddress(&p_xb, g_xb);
    cudaGetSymbolAddress(&p_ahi, g_ahi);
    cudaGetSymbolAddress(&p_alo, g_alo);
    cudaGetSymbolAddress(&p_whi, g_whi);
    cudaGetSymbolAddress(&p_wlo, g_wlo);
    cudaGetSymbolAddress(&p_rhi, g_rhi);
    cudaGetSymbolAddress(&p_rlo, g_rlo);
    float* d_x1 = (float*)p_x1;
    float* d_xb = (float*)p_xb;
    h_ahi = (__nv_bfloat16*)p_ahi;
    h_alo = (__nv_bfloat16*)p_alo;
    h_whi = (__nv_bfloat16*)p_whi;
    h_wlo = (__nv_bfloat16*)p_wlo;
    h_rhi = (__nv_bfloat16*)p_rhi;
    h_rlo = (__nv_bfloat16*)p_rlo;

    // persistent side streams + events (created once; identical work per call)
    static cudaStream_t s_csr = nullptr, s_wt = nullptr;
    static cudaEvent_t s_evFork = nullptr, s_evSeg = nullptr, s_evFill = nullptr;
    static cudaEvent_t s_evW1 = nullptr, s_evW2 = nullptr, s_evW3 = nullptr,
                       s_evW4 = nullptr, s_evW5 = nullptr;
    if (s_csr == nullptr) {
        cudaStreamCreateWithFlags(&s_csr, cudaStreamNonBlocking);
        cudaStreamCreateWithFlags(&s_wt, cudaStreamNonBlocking);
        cudaEventCreateWithFlags(&s_evFork, cudaEventDisableTiming);
        cudaEventCreateWithFlags(&s_evSeg, cudaEventDisableTiming);
        cudaEventCreateWithFlags(&s_evFill, cudaEventDisableTiming);
        cudaEventCreateWithFlags(&s_evW1, cudaEventDisableTiming);
        cudaEventCreateWithFlags(&s_evW2, cudaEventDisableTiming);
        cudaEventCreateWithFlags(&s_evW3, cudaEventDisableTiming);
        cudaEventCreateWithFlags(&s_evW4, cudaEventDisableTiming);
        cudaEventCreateWithFlags(&s_evW5, cudaEventDisableTiming);
    }

    cudaEventRecord(s_evFork, 0);

    // ---- side stream A: segid+zero, CSR build ----
    cudaStreamWaitEvent(s_csr, s_evFork, 0);
    k_segid<<<(NND + 255) / 256, 256, 0, s_csr>>>(sep);
    cudaEventRecord(s_evSeg, s_csr);
    k_hist<<<(NE + 255) / 256, 256, 0, s_csr>>>(dst);
    k_scan<<<1, 1024, 0, s_csr>>>();
    k_fillcsr<<<(NE + 255) / 256, 256, 0, s_csr>>>(src, dst);
    cudaEventRecord(s_evFill, s_csr);

    // ---- side stream B: weight conversions ----
    cudaStreamWaitEvent(s_wt, s_evFork, 0);
    k_cvtW<<<(384 * 192 + 255) / 256, 256, 0, s_wt>>>(w1, h_whi + WOFF_W1, h_wlo + WOFF_W1, D_X, D_0, 384, 192);
    cudaEventRecord(s_evW1, s_wt);
    k_cvtW<<<(256 * 384 + 255) / 256, 256, 0, s_wt>>>(w2, h_whi + WOFF_W2, h_wlo + WOFF_W2, D_GIN, D_X, 256, 384);
    cudaEventRecord(s_evW2, s_wt);
    k_cvtWpair<<<(512 * 512 + 255) / 256, 256, 0, s_wt>>>(wl1, wr1, h_whi + WOFF_S1, h_wlo + WOFF_S1, D_GIN);
    cudaEventRecord(s_evW3, s_wt);
    k_cvtWpair<<<(512 * 1024 + 255) / 256, 256, 0, s_wt>>>(wl2, wr2, h_whi + WOFF_S2, h_wlo + WOFF_S2, D_GH);
    cudaEventRecord(s_evW4, s_wt);
    k_cvtWpair<<<(512 * 1024 + 255) / 256, 256, 0, s_wt>>>(wl3, wr3, h_whi + WOFF_S3, h_wlo + WOFF_S3, D_GH);
    cudaEventRecord(s_evW5, s_wt);

    // ---- main stream: input concat ----
    k_concat_cvt<<<(NND * 192 + 255) / 256, 256>>>(nf, ncf, emb, ops, h_ahi, h_alo);

    // ---- MLP layer 1: needs segid-zeroed stats + W1 ----
    cudaStreamWaitEvent(0, s_evSeg, 0);
    cudaStreamWaitEvent(0, s_evW1, 0);
    run_gemm(h_whi + WOFF_W1, h_wlo + WOFF_W1, b1, d_x1, nullptr, 192, D_X, 384, 2 | 16);
    k_glnapply_cvt<<<dim3(NND, 2), 256>>>(d_x1, g1, be1, D_X, 384, 0, 384, 0, h_ahi, h_alo);

    // ---- MLP layer 2 ----
    cudaStreamWaitEvent(0, s_evW2, 0);
    run_gemm(h_whi + WOFF_W2, h_wlo + WOFF_W2, b2, d_xb, nullptr, 384, D_GIN, 256, 2 | 16 | 64);
    k_glnapply_cvt<<<dim3(NND, 1), 256>>>(d_xb, g2, be2, D_GIN, 256, 256, 512, NS, h_ahi, h_alo);

    // ---- SAGE layer 1: combined K=512 -> raw bf16 + pn-stats ----
    cudaStreamWaitEvent(0, s_evFill, 0);
    k_gather_bf<D_GIN><<<NND / 8, 256>>>(h_ahi, h_alo);
    cudaStreamWaitEvent(0, s_evW3, 0);
    run_gemm(h_whi + WOFF_S1, h_wlo + WOFF_S1, bl1, nullptr, nullptr, 512, D_GH, 512, 8);
    k_pnfin<<<1, 512>>>();

    // ---- SAGE layer 2 ----
    k_gather_pn<<<NND / 8, 256>>>(h_rhi, h_rlo, h_ahi, h_alo);
    cudaStreamWaitEvent(0, s_evW4, 0);
    run_gemm(h_whi + WOFF_S2, h_wlo + WOFF_S2, bl2, nullptr, nullptr, 1024, D_GH, 512, 8);
    k_pnfin<<<1, 512>>>();

    // ---- SAGE layer 3 ----
    k_gather_pn<<<NND / 8, 256>>>(h_rhi, h_rlo, h_ahi, h_alo);
    cudaStreamWaitEvent(0, s_evW5, 0);
    run_gemm(h_whi + WOFF_S3, h_wlo + WOFF_S3, bl3, nullptr, wc, 1024, D_GH, 512, 4);

    k_out<<<1, NS>>>(out, bc);
}